// round 15
// baseline (speedup 1.0000x reference)
#include <cuda_runtime.h>
#include <cuda_bf16.h>
#include <math.h>
#include <stdint.h>

#define NN 50000
#define EE 800000
#define GG 64
#define RR 5
#define BERTD 768
#define HH 128
#define DD 32
#define CCH 2
#define EPSF 1e-5f
#define BETAF 1e-4f
#define KCAT 768   // 5*128 rel + 128 self

// ---------------- scratch (device globals; no allocation) ----------------
__device__ float g_A[NN * HH];
__device__ float g_B[NN * HH];
__device__ float g_Cacc[NN * HH];
__device__ float g_S[NN * KCAT];
__device__ float g_Wcat[KCAT * HH];
__device__ float g_norms[NN];
__device__ float g_normd[NN];
__device__ int g_din[NN];
__device__ int g_dout[NN];
__device__ int g_rowptr[NN + 1];
__device__ int g_cursor[NN];
__device__ int g_eidx[EE];
__device__ int g_gsrc[EE];
__device__ int g_gett[EE];
__device__ int g_pos[EE];
__device__ float g_geatt[EE * 2];
__device__ float g_sum[256];
__device__ float g_sumsq[256];
__device__ float g_scale[256];
__device__ float g_shift[256];
__device__ float g_gsum[2 * GG * HH];
__device__ float g_gcnt[GG];
__device__ float g_xcg[GG * HH];
__device__ float g_xsg[GG * HH];
__device__ float g_h1[GG * 256];
__device__ float g_h2[GG * 256];
__device__ float g_h3[GG * 256];
__device__ float g_xcat[GG * 256];

// ---------------- mma.sync helpers ----------------
__device__ __forceinline__ void ldsm_x4(uint32_t* r, uint32_t addr) {
    asm volatile("ldmatrix.sync.aligned.m8n8.x4.shared.b16 {%0,%1,%2,%3}, [%4];"
                 : "=r"(r[0]), "=r"(r[1]), "=r"(r[2]), "=r"(r[3]) : "r"(addr));
}
__device__ __forceinline__ void ldsm_x2t(uint32_t* r, uint32_t addr) {
    asm volatile("ldmatrix.sync.aligned.m8n8.x2.trans.shared.b16 {%0,%1}, [%2];"
                 : "=r"(r[0]), "=r"(r[1]) : "r"(addr));
}
__device__ __forceinline__ void mma_bf16(float* c, const uint32_t* a, const uint32_t* b) {
    asm volatile(
        "mma.sync.aligned.m16n8k16.row.col.f32.bf16.bf16.f32 "
        "{%0,%1,%2,%3}, {%4,%5,%6,%7}, {%8,%9}, {%0,%1,%2,%3};"
        : "+f"(c[0]), "+f"(c[1]), "+f"(c[2]), "+f"(c[3])
        : "r"(a[0]), "r"(a[1]), "r"(a[2]), "r"(a[3]), "r"(b[0]), "r"(b[1]));
}
__device__ __forceinline__ void split_bf16(float x, __nv_bfloat16& h, __nv_bfloat16& l) {
    h = __float2bfloat16_rn(x);
    l = __float2bfloat16_rn(x - __bfloat162float(h));
}

// ---------------- tensor-core GEMM via mma.sync (bf16x3 split) ----------------
// out[M,128] = A[M,Kin] @ W[Kin,128] (+bias)(relu); optional fused graph pooling.
#define PA 40
#define PB 136
__global__ void __launch_bounds__(256) tgemm(
    const float* __restrict__ A, const float* __restrict__ W,
    const float* __restrict__ bias, float* __restrict__ out,
    int M, int Kin, int doRelu,
    const int* __restrict__ gid, float* __restrict__ gsum) {
    __shared__ __align__(16) __nv_bfloat16 sAh[128 * PA];
    __shared__ __align__(16) __nv_bfloat16 sAl[128 * PA];
    __shared__ __align__(16) __nv_bfloat16 sBh[32 * PB];
    __shared__ __align__(16) __nv_bfloat16 sBl[32 * PB];
    int tid = threadIdx.x, wid = tid >> 5, lane = tid & 31;
    int bm = blockIdx.x * 128;
    int wm = wid & 3, wn = wid >> 2;

    float acc[2][8][4];
#pragma unroll
    for (int i = 0; i < 2; i++)
#pragma unroll
        for (int j = 0; j < 8; j++)
#pragma unroll
            for (int t = 0; t < 4; t++) acc[i][j][t] = 0.f;

    for (int kc = 0; kc < Kin; kc += 32) {
#pragma unroll
        for (int i = 0; i < 4; i++) {
            int idx = tid + i * 256;
            int row = idx >> 3;
            int c4 = idx & 7;
            int grow = bm + row;
            float4 v = make_float4(0.f, 0.f, 0.f, 0.f);
            if (grow < M) v = *(const float4*)(A + (size_t)grow * Kin + kc + (c4 << 2));
            __nv_bfloat16 h0, h1, h2, h3, l0, l1, l2, l3;
            split_bf16(v.x, h0, l0); split_bf16(v.y, h1, l1);
            split_bf16(v.z, h2, l2); split_bf16(v.w, h3, l3);
            __nv_bfloat162 hA = __halves2bfloat162(h0, h1), hB = __halves2bfloat162(h2, h3);
            __nv_bfloat162 lA = __halves2bfloat162(l0, l1), lB = __halves2bfloat162(l2, l3);
            int off = row * PA + (c4 << 2);
            *(uint2*)&sAh[off] = make_uint2(*(uint32_t*)&hA, *(uint32_t*)&hB);
            *(uint2*)&sAl[off] = make_uint2(*(uint32_t*)&lA, *(uint32_t*)&lB);
        }
#pragma unroll
        for (int i = 0; i < 4; i++) {
            int idx = tid + i * 256;
            int row = idx >> 5;
            int c4 = idx & 31;
            float4 v = *(const float4*)(W + (size_t)(kc + row) * 128 + (c4 << 2));
            __nv_bfloat16 h0, h1, h2, h3, l0, l1, l2, l3;
            split_bf16(v.x, h0, l0); split_bf16(v.y, h1, l1);
            split_bf16(v.z, h2, l2); split_bf16(v.w, h3, l3);
            __nv_bfloat162 hA = __halves2bfloat162(h0, h1), hB = __halves2bfloat162(h2, h3);
            __nv_bfloat162 lA = __halves2bfloat162(l0, l1), lB = __halves2bfloat162(l2, l3);
            int off = row * PB + (c4 << 2);
            *(uint2*)&sBh[off] = make_uint2(*(uint32_t*)&hA, *(uint32_t*)&hB);
            *(uint2*)&sBl[off] = make_uint2(*(uint32_t*)&lA, *(uint32_t*)&lB);
        }
        __syncthreads();

#pragma unroll
        for (int ks = 0; ks < 2; ks++) {
            int k0 = ks << 4;
            uint32_t ah[2][4], al[2][4];
            int t4 = lane >> 3, r8 = lane & 7;
            int arow_off = (t4 & 1) * 8 + r8;
            int acol_off = (t4 >> 1) * 8;
#pragma unroll
            for (int mt = 0; mt < 2; mt++) {
                int m0 = wm * 32 + mt * 16;
                int aoff = (m0 + arow_off) * PA + k0 + acol_off;
                ldsm_x4(ah[mt], (uint32_t)__cvta_generic_to_shared(&sAh[aoff]));
                ldsm_x4(al[mt], (uint32_t)__cvta_generic_to_shared(&sAl[aoff]));
            }
            int bt = (lane >> 3) & 1;
#pragma unroll
            for (int nt = 0; nt < 8; nt++) {
                int n0 = wn * 64 + nt * 8;
                int boff = (k0 + bt * 8 + r8) * PB + n0;
                uint32_t bh[2], bl[2];
                ldsm_x2t(bh, (uint32_t)__cvta_generic_to_shared(&sBh[boff]));
                ldsm_x2t(bl, (uint32_t)__cvta_generic_to_shared(&sBl[boff]));
#pragma unroll
                for (int mt = 0; mt < 2; mt++) {
                    mma_bf16(acc[mt][nt], ah[mt], bh);
                    mma_bf16(acc[mt][nt], ah[mt], bl);
                    mma_bf16(acc[mt][nt], al[mt], bh);
                }
            }
        }
        __syncthreads();
    }

    int grp = lane >> 2, qc = (lane & 3) << 1;
#pragma unroll
    for (int mt = 0; mt < 2; mt++) {
#pragma unroll
        for (int nt = 0; nt < 8; nt++) {
            int col = wn * 64 + nt * 8 + qc;
            float b0 = bias ? bias[col] : 0.f;
            float b1 = bias ? bias[col + 1] : 0.f;
#pragma unroll
            for (int hrow = 0; hrow < 2; hrow++) {
                int row = bm + wm * 32 + mt * 16 + grp + hrow * 8;
                if (row < M) {
                    float v0 = acc[mt][nt][hrow * 2 + 0] + b0;
                    float v1 = acc[mt][nt][hrow * 2 + 1] + b1;
                    if (doRelu) { v0 = fmaxf(v0, 0.f); v1 = fmaxf(v1, 0.f); }
                    if (gsum) {
                        int g = gid[row];
                        atomicAdd(&gsum[g * HH + col], v0);
                        atomicAdd(&gsum[g * HH + col + 1], v1);
                    } else {
                        *(float2*)(out + (size_t)row * 128 + col) = make_float2(v0, v1);
                    }
                }
            }
        }
    }
}

// ---------------- fused prologue fill ----------------
__global__ void prologue_fill(int* din, int* dout, int* cursor,
                              float* bsum, float* bsq, float* gcnt, float* gsum) {
    int i = blockIdx.x * blockDim.x + threadIdx.x;
    int stride = gridDim.x * blockDim.x;
    for (int k = i; k < NN; k += stride) { din[k] = 0; dout[k] = 0; cursor[k] = 0; }
    for (int k = i; k < 256; k += stride) { bsum[k] = 0.f; bsq[k] = 0.f; }
    for (int k = i; k < GG; k += stride) gcnt[k] = 0.f;
    for (int k = i; k < 2 * GG * HH; k += stride) gsum[k] = 0.f;
}

__global__ void degree_int(const int* __restrict__ src, const int* __restrict__ dst,
                           int* dout, int* din, int E) {
    int e = blockIdx.x * blockDim.x + threadIdx.x;
    if (e < E) {
        atomicAdd(&dout[src[e]], 1);
        atomicAdd(&din[dst[e]], 1);
    }
}

__global__ void make_norm2(const int* __restrict__ dout, const int* __restrict__ din,
                           float* __restrict__ norms, float* __restrict__ normd, int n) {
    int i = blockIdx.x * blockDim.x + threadIdx.x;
    if (i < n) {
        norms[i] = rsqrtf(fmaxf((float)dout[i], 1.f));
        normd[i] = rsqrtf(fmaxf((float)din[i], 1.f));
    }
}

__global__ void scan_rowptr(const int* __restrict__ cnt, int* __restrict__ rowptr, int n) {
    __shared__ int wsum[32];
    __shared__ int carry;
    int tid = threadIdx.x, lane = tid & 31, wid = tid >> 5;
    if (tid == 0) carry = 0;
    __syncthreads();
    for (int base = 0; base < n; base += 1024) {
        int v = (base + tid < n) ? cnt[base + tid] : 0;
        int inc = v;
#pragma unroll
        for (int off = 1; off < 32; off <<= 1) {
            int t = __shfl_up_sync(0xffffffffu, inc, off);
            if (lane >= off) inc += t;
        }
        if (lane == 31) wsum[wid] = inc;
        __syncthreads();
        if (wid == 0) {
            int s = wsum[lane];
            int si = s;
#pragma unroll
            for (int off = 1; off < 32; off <<= 1) {
                int t = __shfl_up_sync(0xffffffffu, si, off);
                if (lane >= off) si += t;
            }
            wsum[lane] = si - s;
        }
        __syncthreads();
        int excl = carry + wsum[wid] + inc - v;
        if (base + tid < n) rowptr[base + tid] = excl;
        __syncthreads();
        if (tid == 1023) carry = excl + v;
        __syncthreads();
    }
    if (threadIdx.x == 0) rowptr[n] = carry;
}

__global__ void build_eidx(const int* __restrict__ dst, const int* __restrict__ src,
                           const int* __restrict__ et, const int* __restrict__ rowptr,
                           int* __restrict__ cursor, int* __restrict__ eidx,
                           int* __restrict__ gsrc, int* __restrict__ gett,
                           int* __restrict__ pos, int E) {
    int e = blockIdx.x * blockDim.x + threadIdx.x;
    if (e < E) {
        int d = dst[e];
        int p = rowptr[d] + atomicAdd(&cursor[d], 1);
        eidx[p] = e;
        gsrc[p] = src[e];
        gett[p] = et[e];
        pos[e] = p;
    }
}

__global__ void build_wcat(const float* __restrict__ Wrel, const float* __restrict__ Wself,
                           float* __restrict__ Wcat) {
    int i = blockIdx.x * blockDim.x + threadIdx.x;
    if (i < RR * HH * HH) Wcat[i] = Wrel[i];
    else if (i < KCAT * HH) Wcat[i] = Wself[i - RR * HH * HH];
}

// ---------------- BatchNorm stats ----------------
__global__ void bn_stats(const float* __restrict__ X, int M,
                         float* sum, float* sumsq) {
    int j = threadIdx.x;  // 128
    float s = 0.f, s2 = 0.f;
    for (int m = blockIdx.x; m < M; m += gridDim.x) {
        float v = X[(size_t)m * HH + j];
        s += v; s2 += v * v;
    }
    atomicAdd(&sum[j], s);
    atomicAdd(&sumsq[j], s2);
}

__global__ void bn_stats2(const float* __restrict__ X, const float* __restrict__ natt,
                          int M, float* sum, float* sumsq) {
    int j = threadIdx.x;  // 128
    float s0 = 0.f, q0 = 0.f, s1 = 0.f, q1 = 0.f;
    for (int m = blockIdx.x; m < M; m += gridDim.x) {
        float x = X[(size_t)m * HH + j];
        float na0 = natt[2 * m], na1 = natt[2 * m + 1];
        float v0 = x * na0, v1 = x * na1;
        s0 += v0; q0 += v0 * v0;
        s1 += v1; q1 += v1 * v1;
    }
    atomicAdd(&sum[j], s0);       atomicAdd(&sumsq[j], q0);
    atomicAdd(&sum[128 + j], s1); atomicAdd(&sumsq[128 + j], q1);
}

// computes scale/shift AND zeroes sum/sumsq for the next use (saves fill launches)
__global__ void bn_fin(float* sum, float* sumsq, float invM, int K,
                       float* scale, float* shift) {
    int j = blockIdx.x * blockDim.x + threadIdx.x;
    if (j < K) {
        float mean = sum[j] * invM;
        float var = sumsq[j] * invM - mean * mean;
        float sc = rsqrtf(var + EPSF);
        scale[j] = sc;
        shift[j] = BETAF - mean * sc;
        sum[j] = 0.f;
        sumsq[j] = 0.f;
    }
}

// ---------------- fused CSR aggregation (batch-4 pipelined, no atomics) ----------------
__global__ void csr_rel_gather_bn(const float* __restrict__ X,
                                  const float* __restrict__ scale, const float* __restrict__ shift,
                                  const int* __restrict__ gsrc, const int* __restrict__ gett,
                                  const int* __restrict__ rowptr,
                                  float* __restrict__ S, int Nn) {
    int gw = (blockIdx.x * blockDim.x + threadIdx.x) >> 5;
    if (gw >= Nn) return;
    int c = (threadIdx.x & 31) << 2;
    float4 sc = *(const float4*)(scale + c);
    float4 sh = *(const float4*)(shift + c);
    float4 a0 = make_float4(0, 0, 0, 0), a1 = a0, a2 = a0, a3 = a0, a4 = a0;
    int j0 = rowptr[gw], j1 = rowptr[gw + 1];
    int j = j0;
#define RELACC(xx, rr)                                                        \
    {                                                                         \
        float4 v;                                                             \
        v.x = fmaf(xx.x, sc.x, sh.x); v.y = fmaf(xx.y, sc.y, sh.y);           \
        v.z = fmaf(xx.z, sc.z, sh.z); v.w = fmaf(xx.w, sc.w, sh.w);           \
        if (rr == 0)      { a0.x += v.x; a0.y += v.y; a0.z += v.z; a0.w += v.w; } \
        else if (rr == 1) { a1.x += v.x; a1.y += v.y; a1.z += v.z; a1.w += v.w; } \
        else if (rr == 2) { a2.x += v.x; a2.y += v.y; a2.z += v.z; a2.w += v.w; } \
        else if (rr == 3) { a3.x += v.x; a3.y += v.y; a3.z += v.z; a3.w += v.w; } \
        else              { a4.x += v.x; a4.y += v.y; a4.z += v.z; a4.w += v.w; } \
    }
    for (; j + 3 < j1; j += 4) {
        int s0 = gsrc[j], s1 = gsrc[j + 1], s2 = gsrc[j + 2], s3 = gsrc[j + 3];
        int r0 = gett[j], r1 = gett[j + 1], r2 = gett[j + 2], r3 = gett[j + 3];
        float4 x0 = *(const float4*)(X + (size_t)s0 * HH + c);
        float4 x1 = *(const float4*)(X + (size_t)s1 * HH + c);
        float4 x2 = *(const float4*)(X + (size_t)s2 * HH + c);
        float4 x3 = *(const float4*)(X + (size_t)s3 * HH + c);
        RELACC(x0, r0) RELACC(x1, r1) RELACC(x2, r2) RELACC(x3, r3)
    }
    for (; j < j1; j++) {
        int s = gsrc[j];
        int r = gett[j];
        float4 x = *(const float4*)(X + (size_t)s * HH + c);
        RELACC(x, r)
    }
#undef RELACC
    float4 xs = *(const float4*)(X + (size_t)gw * HH + c);
    float4 sv;
    sv.x = fmaf(xs.x, sc.x, sh.x); sv.y = fmaf(xs.y, sc.y, sh.y);
    sv.z = fmaf(xs.z, sc.z, sh.z); sv.w = fmaf(xs.w, sc.w, sh.w);
    float* Sp = S + (size_t)gw * KCAT + c;
    *(float4*)(Sp + 0)   = a0;
    *(float4*)(Sp + 128) = a1;
    *(float4*)(Sp + 256) = a2;
    *(float4*)(Sp + 384) = a3;
    *(float4*)(Sp + 512) = a4;
    *(float4*)(Sp + 640) = sv;
}

__global__ void csr_gather_bn(const float* __restrict__ X,
                              const float* __restrict__ scale, const float* __restrict__ shift,
                              const float* __restrict__ norms,
                              const int* __restrict__ gsrc, const int* __restrict__ rowptr,
                              const float* __restrict__ normd, float* __restrict__ out, int Nn) {
    int gw = (blockIdx.x * blockDim.x + threadIdx.x) >> 5;
    if (gw >= Nn) return;
    int c = (threadIdx.x & 31) << 2;
    float4 sc = *(const float4*)(scale + c);
    float4 sh = *(const float4*)(shift + c);
    float ax = 0.f, ay = 0.f, az = 0.f, aw = 0.f;
    int j0 = rowptr[gw], j1 = rowptr[gw + 1];
    int j = j0;
#define GACC(xx, nn)                                  \
    {                                                 \
        ax += fmaf(xx.x, sc.x, sh.x) * nn;            \
        ay += fmaf(xx.y, sc.y, sh.y) * nn;            \
        az += fmaf(xx.z, sc.z, sh.z) * nn;            \
        aw += fmaf(xx.w, sc.w, sh.w) * nn;            \
    }
    for (; j + 3 < j1; j += 4) {
        int s0 = gsrc[j], s1 = gsrc[j + 1], s2 = gsrc[j + 2], s3 = gsrc[j + 3];
        float n0 = norms[s0], n1 = norms[s1], n2 = norms[s2], n3 = norms[s3];
        float4 x0 = *(const float4*)(X + (size_t)s0 * HH + c);
        float4 x1 = *(const float4*)(X + (size_t)s1 * HH + c);
        float4 x2 = *(const float4*)(X + (size_t)s2 * HH + c);
        float4 x3 = *(const float4*)(X + (size_t)s3 * HH + c);
        GACC(x0, n0) GACC(x1, n1) GACC(x2, n2) GACC(x3, n3)
    }
    for (; j < j1; j++) {
        int s = gsrc[j];
        float ns = norms[s];
        float4 x = *(const float4*)(X + (size_t)s * HH + c);
        GACC(x, ns)
    }
#undef GACC
    float nd = normd[gw];
    *(float4*)(out + (size_t)gw * HH + c) = make_float4(ax * nd, ay * nd, az * nd, aw * nd);
}

__global__ void csr_gather_bn2(const float* __restrict__ X, const float* __restrict__ natt,
                               const float* __restrict__ scale, const float* __restrict__ shift,
                               const float* __restrict__ norms,
                               const int* __restrict__ gsrc, const int* __restrict__ rowptr,
                               const float* __restrict__ geatt,
                               const float* __restrict__ normd,
                               float* __restrict__ outc, float* __restrict__ outs, int Nn) {
    int gw = (blockIdx.x * blockDim.x + threadIdx.x) >> 5;
    if (gw >= Nn) return;
    int c = (threadIdx.x & 31) << 2;
    float4 sc0 = *(const float4*)(scale + c);
    float4 sh0 = *(const float4*)(shift + c);
    float4 sc1 = *(const float4*)(scale + 128 + c);
    float4 sh1 = *(const float4*)(shift + 128 + c);
    float cx = 0.f, cy = 0.f, cz = 0.f, cw = 0.f;
    float sx = 0.f, sy = 0.f, sz = 0.f, sw = 0.f;
    int j0 = rowptr[gw], j1 = rowptr[gw + 1];
    int j = j0;
#define BACC(xx, nat, nn, ww)                                         \
    {                                                                 \
        float f0 = nat.x * nn, f1 = nat.y * nn;                       \
        cx += ww.x * fmaf(xx.x, sc0.x * f0, sh0.x * nn);              \
        cy += ww.x * fmaf(xx.y, sc0.y * f0, sh0.y * nn);              \
        cz += ww.x * fmaf(xx.z, sc0.z * f0, sh0.z * nn);              \
        cw += ww.x * fmaf(xx.w, sc0.w * f0, sh0.w * nn);              \
        sx += ww.y * fmaf(xx.x, sc1.x * f1, sh1.x * nn);              \
        sy += ww.y * fmaf(xx.y, sc1.y * f1, sh1.y * nn);              \
        sz += ww.y * fmaf(xx.z, sc1.z * f1, sh1.z * nn);              \
        sw += ww.y * fmaf(xx.w, sc1.w * f1, sh1.w * nn);              \
    }
    for (; j + 3 < j1; j += 4) {
        int s0 = gsrc[j], s1 = gsrc[j + 1], s2 = gsrc[j + 2], s3 = gsrc[j + 3];
        float2 w0 = *(const float2*)(geatt + 2 * j);
        float2 w1 = *(const float2*)(geatt + 2 * (j + 1));
        float2 w2 = *(const float2*)(geatt + 2 * (j + 2));
        float2 w3 = *(const float2*)(geatt + 2 * (j + 3));
        float n0 = norms[s0], n1 = norms[s1], n2 = norms[s2], n3 = norms[s3];
        float2 t0 = *(const float2*)(natt + 2 * s0);
        float2 t1 = *(const float2*)(natt + 2 * s1);
        float2 t2 = *(const float2*)(natt + 2 * s2);
        float2 t3 = *(const float2*)(natt + 2 * s3);
        float4 x0 = *(const float4*)(X + (size_t)s0 * HH + c);
        float4 x1 = *(const float4*)(X + (size_t)s1 * HH + c);
        float4 x2 = *(const float4*)(X + (size_t)s2 * HH + c);
        float4 x3 = *(const float4*)(X + (size_t)s3 * HH + c);
        BACC(x0, t0, n0, w0) BACC(x1, t1, n1, w1)
        BACC(x2, t2, n2, w2) BACC(x3, t3, n3, w3)
    }
    for (; j < j1; j++) {
        int s = gsrc[j];
        float2 w = *(const float2*)(geatt + 2 * j);
        float ns = norms[s];
        float2 t = *(const float2*)(natt + 2 * s);
        float4 x = *(const float4*)(X + (size_t)s * HH + c);
        BACC(x, t, ns, w)
    }
#undef BACC
    float nd = normd[gw];
    *(float4*)(outc + (size_t)gw * HH + c) = make_float4(cx * nd, cy * nd, cz * nd, cw * nd);
    *(float4*)(outs + (size_t)gw * HH + c) = make_float4(sx * nd, sy * nd, sz * nd, sw * nd);
}

// ---------------- attention kernels ----------------
__global__ void node_att_kernel(const float* __restrict__ x, const float* __restrict__ W,
                                const float* __restrict__ b, float* __restrict__ natt, int Nn) {
    __shared__ float Ws[256];
    for (int i = threadIdx.x; i < 256; i += blockDim.x) Ws[i] = W[i];
    __syncthreads();
    int gi = blockIdx.x * blockDim.x + threadIdx.x;
    int n = gi >> 5, lane = threadIdx.x & 31;
    if (n >= Nn) return;
    float4 xv = *(const float4*)(x + (size_t)n * HH + (lane << 2));
    float vv[4] = {xv.x, xv.y, xv.z, xv.w};
    float s0 = 0.f, s1 = 0.f;
#pragma unroll
    for (int t = 0; t < 4; t++) {
        int k = (lane << 2) + t;
        s0 = fmaf(vv[t], Ws[k * 2 + 0], s0);
        s1 = fmaf(vv[t], Ws[k * 2 + 1], s1);
    }
    for (int o = 16; o > 0; o >>= 1) {
        s0 += __shfl_down_sync(0xffffffffu, s0, o);
        s1 += __shfl_down_sync(0xffffffffu, s1, o);
    }
    if (lane == 0) {
        float z0 = s0 + b[0], z1 = s1 + b[1];
        float m = fmaxf(z0, z1);
        float e0 = expf(z0 - m), e1 = expf(z1 - m);
        float inv = 1.f / (e0 + e1);
        natt[(size_t)n * 2 + 0] = e0 * inv;
        natt[(size_t)n * 2 + 1] = e1 * inv;
    }
}

__global__ void edge_att_kernel(const float* __restrict__ x, const int* __restrict__ src,
                                const int* __restrict__ dst, const float* __restrict__ W,
                                const float* __restrict__ b, const int* __restrict__ pos,
                                float* __restrict__ eatt, float* __restrict__ geatt, int E) {
    __shared__ float Ws[512];
    for (int i = threadIdx.x; i < 512; i += blockDim.x) Ws[i] = W[i];
    __syncthreads();
    int gi = blockIdx.x * blockDim.x + threadIdx.x;
    int e = gi >> 5, lane = threadIdx.x & 31;
    if (e >= E) return;
    int s = src[e], d = dst[e];
    float4 xs = *(const float4*)(x + (size_t)s * HH + (lane << 2));
    float4 xd = *(const float4*)(x + (size_t)d * HH + (lane << 2));
    float vs[4] = {xs.x, xs.y, xs.z, xs.w};
    float vd[4] = {xd.x, xd.y, xd.z, xd.w};
    float s0 = 0.f, s1 = 0.f;
#pragma unroll
    for (int t = 0; t < 4; t++) {
        int k = (lane << 2) + t;
        s0 = fmaf(vs[t], Ws[k * 2 + 0], s0);
        s1 = fmaf(vs[t], Ws[k * 2 + 1], s1);
        s0 = fmaf(vd[t], Ws[(128 + k) * 2 + 0], s0);
        s1 = fmaf(vd[t], Ws[(128 + k) * 2 + 1], s1);
    }
    for (int o = 16; o > 0; o >>= 1) {
        s0 += __shfl_down_sync(0xffffffffu, s0, o);
        s1 += __shfl_down_sync(0xffffffffu, s1, o);
    }
    if (lane == 0) {
        float z0 = s0 + b[0], z1 = s1 + b[1];
        float m = fmaxf(z0, z1);
        float e0 = expf(z0 - m), e1 = expf(z1 - m);
        float inv = 1.f / (e0 + e1);
        float w0 = e0 * inv, w1 = e1 * inv;
        eatt[(size_t)e * 2 + 0] = w0;
        eatt[(size_t)e * 2 + 1] = w1;
        int p = pos[e];
        geatt[(size_t)p * 2 + 0] = w0;
        geatt[(size_t)p * 2 + 1] = w1;
    }
}

// ---------------- per-graph mean ----------------
__global__ void gcount_kernel(const int* __restrict__ gid, float* gcnt, int Nn) {
    int n = blockIdx.x * blockDim.x + threadIdx.x;
    if (n < Nn) atomicAdd(&gcnt[gid[n]], 1.f);
}

// finalize both branches in one launch
__global__ void graph_div2(const float* gsum, const float* gcnt,
                           float* xcg, float* xsg, float* oc, float* os) {
    int i = blockIdx.x * blockDim.x + threadIdx.x;
    if (i >= GG * HH) return;
    int g = i / HH;
    float inv = 1.f / fmaxf(gcnt[g], 1.f);
    float v = gsum[i] * inv;
    float w = gsum[GG * HH + i] * inv;
    xcg[i] = v; oc[i] = v;
    xsg[i] = w; os[i] = w;
}

// ---------------- fused heads (single block) ----------------
__device__ __forceinline__ void threefry2x32(uint32_t k0, uint32_t k1, uint32_t x0, uint32_t x1,
                                             uint32_t* o0, uint32_t* o1) {
    uint32_t ks[3] = {k0, k1, k0 ^ k1 ^ 0x1BD11BDAu};
    const int r1[4] = {13, 15, 26, 6};
    const int r2[4] = {17, 29, 16, 24};
    x0 += ks[0]; x1 += ks[1];
#pragma unroll
    for (int i = 0; i < 5; i++) {
        const int* rot = (i % 2 == 0) ? r1 : r2;
#pragma unroll
        for (int j = 0; j < 4; j++) {
            x0 += x1;
            x1 = (x1 << rot[j]) | (x1 >> (32 - rot[j]));
            x1 ^= x0;
        }
        x0 += ks[(i + 1) % 3];
        x1 += ks[(i + 2) % 3] + (uint32_t)(i + 1);
    }
    *o0 = x0; *o1 = x1;
}

__device__ void blk_bn(const float* in, float* out, int K) {
    int j = threadIdx.x;
    if (j < K) {
        float s = 0.f, s2 = 0.f;
        for (int m = 0; m < GG; m++) {
            float v = in[m * K + j];
            s += v; s2 += v * v;
        }
        float mean = s / GG;
        float var = s2 / GG - mean * mean;
        float r = rsqrtf(var + EPSF);
        for (int m = 0; m < GG; m++)
            out[m * K + j] = (in[m * K + j] - mean) * r + BETAF;
    }
    __syncthreads();
}

__device__ void blk_fc(const float* A, const float* W, const float* b, float* C,
                       int Kin, int Kout, int doRelu) {
    for (int i = threadIdx.x; i < GG * Kout; i += blockDim.x) {
        int m = i / Kout, j = i - m * Kout;
        float s = b ? b[j] : 0.f;
        for (int k = 0; k < Kin; k++) s = fmaf(A[m * Kin + k], W[k * Kout + j], s);
        C[i] = doRelu ? fmaxf(s, 0.f) : s;
    }
    __syncthreads();
}

__global__ void heads_kernel(
    const float* __restrict__ xcg, const float* __restrict__ xsg,
    const float* cfc1W, const float* cfc1b, const float* cfc2W, const float* cfc2b,
    const float* sfc1W, const float* sfc1b, const float* sfc2W, const float* sfc2b,
    const float* ccat1W, const float* ccat1b, const float* ccat2W, const float* ccat2b,
    float* h1, float* h2, float* h3, float* xcat,
    float* out_causal, float* out_spur, float* out_ctx) {
    __shared__ uint32_t keys[64];
    __shared__ int sperm[64];
    int tid = threadIdx.x;
    if (tid < 64) {
        uint32_t sk0, sk1, o0, o1;
        threefry2x32(0u, 42u, 0u, 1u, &sk0, &sk1);
        threefry2x32(sk0, sk1, 0u, (uint32_t)tid, &o0, &o1);
        keys[tid] = o0 ^ o1;
    }
    __syncthreads();
    if (tid < 64) {
        uint32_t ki = keys[tid];
        int rank = 0;
        for (int j = 0; j < 64; j++) {
            uint32_t kj = keys[j];
            rank += (kj < ki) || (kj == ki && j < tid);
        }
        sperm[rank] = tid;
    }
    __syncthreads();

    // causal head
    blk_bn(xcg, h1, 128);
    blk_fc(h1, cfc1W, cfc1b, h2, 128, DD, 1);
    blk_bn(h2, h3, DD);
    blk_fc(h3, cfc2W, cfc2b, out_causal, DD, CCH, 0);

    // spurious head
    blk_bn(xsg, h1, 128);
    blk_fc(h1, sfc1W, sfc1b, h2, 128, DD, 1);
    blk_bn(h2, h3, DD);
    blk_fc(h3, sfc2W, sfc2b, h2, DD, CCH, 0);
    if (tid < GG) {
        float z0 = h2[tid * 2], z1 = h2[tid * 2 + 1];
        float m = fmaxf(z0, z1);
        float l = m + logf(expf(z0 - m) + expf(z1 - m));
        out_spur[tid * 2] = z0 - l;
        out_spur[tid * 2 + 1] = z1 - l;
    }
    __syncthreads();

    // context head
    for (int i = tid; i < GG * 256; i += blockDim.x) {
        int g = i >> 8, c = i & 255;
        xcat[i] = (c < HH) ? xcg[g * HH + c] : xsg[sperm[g] * HH + (c - HH)];
    }
    __syncthreads();
    blk_bn(xcat, h1, 256);
    blk_fc(h1, ccat1W, ccat1b, h2, 256, DD, 1);
    blk_bn(h2, h3, DD);
    blk_fc(h3, ccat2W, ccat2b, out_ctx, DD, CCH, 0);
}

// ---------------- launch ----------------
extern "C" void kernel_launch(void* const* d_in, const int* in_sizes, int n_in,
                              void* d_out, int out_size) {
    const float* feat = nullptr;
    const int *src = nullptr, *dst = nullptr, *et = nullptr, *gid = nullptr;
    const float* Wp[27];
    int wi = 0, eseen = 0;
    for (int i = 0; i < n_in; i++) {
        int sz = in_sizes[i];
        if (sz == NN * BERTD) feat = (const float*)d_in[i];
        else if (sz == EE) {
            if (eseen == 0) src = (const int*)d_in[i];
            else if (eseen == 1) dst = (const int*)d_in[i];
            else et = (const int*)d_in[i];
            eseen++;
        } else if (sz == NN) gid = (const int*)d_in[i];
        else if (wi < 27) Wp[wi++] = (const float*)d_in[i];
    }
    const float *W_red = Wp[0], *b_red = Wp[1], *W_rel = Wp[2], *W_self = Wp[3], *b_rel = Wp[4];
    const float *W_conv = Wp[5], *b_conv = Wp[6], *W_eatt = Wp[7], *b_eatt = Wp[8];
    const float *W_natt = Wp[9], *b_natt = Wp[10], *W_cconv = Wp[11], *b_cconv = Wp[12];
    const float *W_sconv = Wp[13], *b_sconv = Wp[14];
    const float *cfc1W = Wp[15], *cfc1b = Wp[16], *cfc2W = Wp[17], *cfc2b = Wp[18];
    const float *sfc1W = Wp[19], *sfc1b = Wp[20], *sfc2W = Wp[21], *sfc2b = Wp[22];
    const float *ccat1W = Wp[23], *ccat1b = Wp[24], *ccat2W = Wp[25], *ccat2b = Wp[26];

    float *A, *B, *Cc, *S, *Wcat, *norms, *normd, *bsum, *bsq, *bsc, *bsh;
    float *gsum, *gcnt, *xcg, *xsg, *h1, *h2, *h3, *xcat, *geatt;
    int *din, *dout, *rowptr, *cursor, *eidx, *gsrc, *gett, *pos;
    cudaGetSymbolAddress((void**)&A, g_A);
    cudaGetSymbolAddress((void**)&B, g_B);
    cudaGetSymbolAddress((void**)&Cc, g_Cacc);
    cudaGetSymbolAddress((void**)&S, g_S);
    cudaGetSymbolAddress((void**)&Wcat, g_Wcat);
    cudaGetSymbolAddress((void**)&norms, g_norms);
    cudaGetSymbolAddress((void**)&normd, g_normd);
    cudaGetSymbolAddress((void**)&din, g_din);
    cudaGetSymbolAddress((void**)&dout, g_dout);
    cudaGetSymbolAddress((void**)&rowptr, g_rowptr);
    cudaGetSymbolAddress((void**)&cursor, g_cursor);
    cudaGetSymbolAddress((void**)&eidx, g_eidx);
    cudaGetSymbolAddress((void**)&gsrc, g_gsrc);
    cudaGetSymbolAddress((void**)&gett, g_gett);
    cudaGetSymbolAddress((void**)&pos, g_pos);
    cudaGetSymbolAddress((void**)&geatt, g_geatt);
    cudaGetSymbolAddress((void**)&bsum, g_sum);
    cudaGetSymbolAddress((void**)&bsq, g_sumsq);
    cudaGetSymbolAddress((void**)&bsc, g_scale);
    cudaGetSymbolAddress((void**)&bsh, g_shift);
    cudaGetSymbolAddress((void**)&gsum, g_gsum);
    cudaGetSymbolAddress((void**)&gcnt, g_gcnt);
    cudaGetSymbolAddress((void**)&xcg, g_xcg);
    cudaGetSymbolAddress((void**)&xsg, g_xsg);
    cudaGetSymbolAddress((void**)&h1, g_h1);
    cudaGetSymbolAddress((void**)&h2, g_h2);
    cudaGetSymbolAddress((void**)&h3, g_h3);
    cudaGetSymbolAddress((void**)&xcat, g_xcat);

    float* out = (float*)d_out;
    float* out_causal = out;
    float* out_spur = out + GG * CCH;
    float* out_ctx = out + 2 * GG * CCH;
    float* out_xcg = out + 3 * GG * CCH;
    float* out_xsg = out_xcg + GG * HH;
    float* out_natt = out_xsg + GG * HH;
    float* out_eatt = out_natt + NN * 2;

    const int gemmGrid = (NN + 127) / 128;
    const int edgeWGrid = (EE * 32 + 255) / 256;
    const int nodeWGrid = (NN * 32 + 255) / 256;
    const int gatherGrid = (NN + 7) / 8;

    // one fused prologue fill (din/dout/cursor/bsum/bsq/gcnt/gsum both halves)
    prologue_fill<<<256, 256>>>(din, dout, cursor, bsum, bsq, gcnt, gsum);

    // feat reduce GEMM
    tgemm<<<gemmGrid, 256>>>(feat, W_red, b_red, A, NN, BERTD, 0, nullptr, nullptr);

    // CSR build + degree norms
    degree_int<<<(EE + 255) / 256, 256>>>(src, dst, dout, din, EE);
    make_norm2<<<(NN + 255) / 256, 256>>>(dout, din, norms, normd, NN);
    scan_rowptr<<<1, 1024>>>(din, rowptr, NN);
    build_eidx<<<(EE + 255) / 256, 256>>>(dst, src, et, rowptr, cursor, eidx, gsrc, gett, pos, EE);
    build_wcat<<<(KCAT * HH + 255) / 256, 256>>>(W_rel, W_self, Wcat);

    gcount_kernel<<<(NN + 255) / 256, 256>>>(gid, gcnt, NN);

    bn_stats<<<512, 128>>>(A, NN, bsum, bsq);
    bn_fin<<<1, 128>>>(bsum, bsq, 1.f / NN, 128, bsc, bsh);

    // RelGraphConv (aggregate-first, BN inline)
    csr_rel_gather_bn<<<gatherGrid, 256>>>(A, bsc, bsh, gsrc, gett, rowptr, S, NN);
    tgemm<<<gemmGrid, 256>>>(S, Wcat, b_rel, A, NN, KCAT, 1, nullptr, nullptr);

    // two GraphConv layers (BN fused into gather; bn_fin self-cleans stats)
    for (int i = 0; i < 2; i++) {
        bn_stats<<<512, 128>>>(A, NN, bsum, bsq);
        bn_fin<<<1, 128>>>(bsum, bsq, 1.f / NN, 128, bsc, bsh);
        csr_gather_bn<<<gatherGrid, 256>>>(A, bsc, bsh, norms, gsrc, rowptr, normd, Cc, NN);
        tgemm<<<gemmGrid, 256>>>(Cc, W_conv + (size_t)i * HH * HH, b_conv + i * HH, A, NN, HH, 1,
                                 nullptr, nullptr);
    }

    // attentions
    node_att_kernel<<<nodeWGrid, 256>>>(A, W_natt, b_natt, out_natt, NN);
    edge_att_kernel<<<edgeWGrid, 256>>>(A, src, dst, W_eatt, b_eatt, pos, out_eatt, geatt, EE);

    // both branches: one stats pass + one fused gather pass
    bn_stats2<<<512, 128>>>(A, out_natt, NN, bsum, bsq);
    bn_fin<<<1, 256>>>(bsum, bsq, 1.f / NN, 256, bsc, bsh);
    csr_gather_bn2<<<gatherGrid, 256>>>(A, out_natt, bsc, bsh, norms, gsrc, rowptr,
                                        geatt, normd, Cc, B, NN);

    // branch GEMMs with fused pooling (gsum halves pre-zeroed in prologue)
    tgemm<<<gemmGrid, 256>>>(Cc, W_cconv, b_cconv, nullptr, NN, HH, 1, gid, gsum);
    tgemm<<<gemmGrid, 256>>>(B, W_sconv, b_sconv, nullptr, NN, HH, 1, gid, gsum + GG * HH);
    graph_div2<<<(GG * HH + 255) / 256, 256>>>(gsum, gcnt, xcg, xsg, out_xcg, out_xsg);

    // all three heads in one fused single-block kernel
    heads_kernel<<<1, 256>>>(xcg, xsg,
                             cfc1W, cfc1b, cfc2W, cfc2b,
                             sfc1W, sfc1b, sfc2W, sfc2b,
                             ccat1W, ccat1b, ccat2W, ccat2b,
                             h1, h2, h3, xcat,
                             out_causal, out_spur, out_ctx);
}

// round 16
// speedup vs baseline: 1.0143x; 1.0143x over previous
#include <cuda_runtime.h>
#include <cuda_bf16.h>
#include <math.h>
#include <stdint.h>

#define NN 50000
#define EE 800000
#define GG 64
#define RR 5
#define BERTD 768
#define HH 128
#define DD 32
#define CCH 2
#define EPSF 1e-5f
#define BETAF 1e-4f
#define KCAT 768   // 5*128 rel + 128 self

// ---------------- scratch (device globals; no allocation) ----------------
__device__ float g_A[NN * HH];
__device__ float g_B[NN * HH];
__device__ float g_Cacc[NN * HH];
__device__ float g_S[NN * KCAT];
__device__ float g_Wcat[KCAT * HH];
__device__ float g_norms[NN];
__device__ float g_normd[NN];
__device__ int g_din[NN];
__device__ int g_dout[NN];
__device__ int g_rowptr[NN + 1];
__device__ int g_cursor[NN];
__device__ int g_eidx[EE];
__device__ int g_gsrc[EE];
__device__ int g_gett[EE];
__device__ int g_pos[EE];
__device__ float g_geatt[EE * 2];
__device__ float g_sum[1024];     // stats slots: 0=feat,128=conv1,256=conv2,384..639=branch2
__device__ float g_sumsq[1024];
__device__ float g_gsum[2 * GG * HH];
__device__ float g_gcnt[GG];
__device__ float g_xcg[GG * HH];
__device__ float g_xsg[GG * HH];
__device__ float g_h1[GG * 256];
__device__ float g_h2[GG * 256];
__device__ float g_h3[GG * 256];
__device__ float g_xcat[GG * 256];

// ---------------- mma.sync helpers ----------------
__device__ __forceinline__ void ldsm_x4(uint32_t* r, uint32_t addr) {
    asm volatile("ldmatrix.sync.aligned.m8n8.x4.shared.b16 {%0,%1,%2,%3}, [%4];"
                 : "=r"(r[0]), "=r"(r[1]), "=r"(r[2]), "=r"(r[3]) : "r"(addr));
}
__device__ __forceinline__ void ldsm_x2t(uint32_t* r, uint32_t addr) {
    asm volatile("ldmatrix.sync.aligned.m8n8.x2.trans.shared.b16 {%0,%1}, [%2];"
                 : "=r"(r[0]), "=r"(r[1]) : "r"(addr));
}
__device__ __forceinline__ void mma_bf16(float* c, const uint32_t* a, const uint32_t* b) {
    asm volatile(
        "mma.sync.aligned.m16n8k16.row.col.f32.bf16.bf16.f32 "
        "{%0,%1,%2,%3}, {%4,%5,%6,%7}, {%8,%9}, {%0,%1,%2,%3};"
        : "+f"(c[0]), "+f"(c[1]), "+f"(c[2]), "+f"(c[3])
        : "r"(a[0]), "r"(a[1]), "r"(a[2]), "r"(a[3]), "r"(b[0]), "r"(b[1]));
}
__device__ __forceinline__ void split_bf16(float x, __nv_bfloat16& h, __nv_bfloat16& l) {
    h = __float2bfloat16_rn(x);
    l = __float2bfloat16_rn(x - __bfloat162float(h));
}
// inline BN coefficient computation from raw sums (matches old bn_fin exactly)
__device__ __forceinline__ void bn_coef4(const float* sum, const float* sumsq, int c,
                                         float invM, float4& sc, float4& sh) {
    float4 s4 = *(const float4*)(sum + c);
    float4 q4 = *(const float4*)(sumsq + c);
    float m0 = s4.x * invM, m1 = s4.y * invM, m2 = s4.z * invM, m3 = s4.w * invM;
    sc.x = rsqrtf(q4.x * invM - m0 * m0 + EPSF);
    sc.y = rsqrtf(q4.y * invM - m1 * m1 + EPSF);
    sc.z = rsqrtf(q4.z * invM - m2 * m2 + EPSF);
    sc.w = rsqrtf(q4.w * invM - m3 * m3 + EPSF);
    sh.x = BETAF - m0 * sc.x; sh.y = BETAF - m1 * sc.y;
    sh.z = BETAF - m2 * sc.z; sh.w = BETAF - m3 * sc.w;
}

// ---------------- tensor-core GEMM via mma.sync (bf16x3 split) ----------------
// out[M,128] = A[M,Kin] @ W[Kin,128] (+bias)(relu); optional fused graph pooling.
// If gridHalf>0, blocks >= gridHalf process (A2, W2, bias2, gsum2) instead.
#define PA 40
#define PB 136
__global__ void __launch_bounds__(256) tgemm(
    const float* __restrict__ A, const float* __restrict__ W,
    const float* __restrict__ bias, float* __restrict__ out,
    int M, int Kin, int doRelu,
    const int* __restrict__ gid, float* __restrict__ gsum,
    const float* __restrict__ A2, const float* __restrict__ W2,
    const float* __restrict__ bias2, float* __restrict__ gsum2, int gridHalf) {
    __shared__ __align__(16) __nv_bfloat16 sAh[128 * PA];
    __shared__ __align__(16) __nv_bfloat16 sAl[128 * PA];
    __shared__ __align__(16) __nv_bfloat16 sBh[32 * PB];
    __shared__ __align__(16) __nv_bfloat16 sBl[32 * PB];
    int tid = threadIdx.x, wid = tid >> 5, lane = tid & 31;
    int bx = blockIdx.x;
    if (gridHalf && bx >= gridHalf) {
        A = A2; W = W2; bias = bias2; gsum = gsum2;
        bx -= gridHalf;
    }
    int bm = bx * 128;
    int wm = wid & 3, wn = wid >> 2;

    float acc[2][8][4];
#pragma unroll
    for (int i = 0; i < 2; i++)
#pragma unroll
        for (int j = 0; j < 8; j++)
#pragma unroll
            for (int t = 0; t < 4; t++) acc[i][j][t] = 0.f;

    for (int kc = 0; kc < Kin; kc += 32) {
#pragma unroll
        for (int i = 0; i < 4; i++) {
            int idx = tid + i * 256;
            int row = idx >> 3;
            int c4 = idx & 7;
            int grow = bm + row;
            float4 v = make_float4(0.f, 0.f, 0.f, 0.f);
            if (grow < M) v = *(const float4*)(A + (size_t)grow * Kin + kc + (c4 << 2));
            __nv_bfloat16 h0, h1, h2, h3, l0, l1, l2, l3;
            split_bf16(v.x, h0, l0); split_bf16(v.y, h1, l1);
            split_bf16(v.z, h2, l2); split_bf16(v.w, h3, l3);
            __nv_bfloat162 hA = __halves2bfloat162(h0, h1), hB = __halves2bfloat162(h2, h3);
            __nv_bfloat162 lA = __halves2bfloat162(l0, l1), lB = __halves2bfloat162(l2, l3);
            int off = row * PA + (c4 << 2);
            *(uint2*)&sAh[off] = make_uint2(*(uint32_t*)&hA, *(uint32_t*)&hB);
            *(uint2*)&sAl[off] = make_uint2(*(uint32_t*)&lA, *(uint32_t*)&lB);
        }
#pragma unroll
        for (int i = 0; i < 4; i++) {
            int idx = tid + i * 256;
            int row = idx >> 5;
            int c4 = idx & 31;
            float4 v = *(const float4*)(W + (size_t)(kc + row) * 128 + (c4 << 2));
            __nv_bfloat16 h0, h1, h2, h3, l0, l1, l2, l3;
            split_bf16(v.x, h0, l0); split_bf16(v.y, h1, l1);
            split_bf16(v.z, h2, l2); split_bf16(v.w, h3, l3);
            __nv_bfloat162 hA = __halves2bfloat162(h0, h1), hB = __halves2bfloat162(h2, h3);
            __nv_bfloat162 lA = __halves2bfloat162(l0, l1), lB = __halves2bfloat162(l2, l3);
            int off = row * PB + (c4 << 2);
            *(uint2*)&sBh[off] = make_uint2(*(uint32_t*)&hA, *(uint32_t*)&hB);
            *(uint2*)&sBl[off] = make_uint2(*(uint32_t*)&lA, *(uint32_t*)&lB);
        }
        __syncthreads();

#pragma unroll
        for (int ks = 0; ks < 2; ks++) {
            int k0 = ks << 4;
            uint32_t ah[2][4], al[2][4];
            int t4 = lane >> 3, r8 = lane & 7;
            int arow_off = (t4 & 1) * 8 + r8;
            int acol_off = (t4 >> 1) * 8;
#pragma unroll
            for (int mt = 0; mt < 2; mt++) {
                int m0 = wm * 32 + mt * 16;
                int aoff = (m0 + arow_off) * PA + k0 + acol_off;
                ldsm_x4(ah[mt], (uint32_t)__cvta_generic_to_shared(&sAh[aoff]));
                ldsm_x4(al[mt], (uint32_t)__cvta_generic_to_shared(&sAl[aoff]));
            }
            int bt = (lane >> 3) & 1;
#pragma unroll
            for (int nt = 0; nt < 8; nt++) {
                int n0 = wn * 64 + nt * 8;
                int boff = (k0 + bt * 8 + r8) * PB + n0;
                uint32_t bh[2], bl[2];
                ldsm_x2t(bh, (uint32_t)__cvta_generic_to_shared(&sBh[boff]));
                ldsm_x2t(bl, (uint32_t)__cvta_generic_to_shared(&sBl[boff]));
#pragma unroll
                for (int mt = 0; mt < 2; mt++) {
                    mma_bf16(acc[mt][nt], ah[mt], bh);
                    mma_bf16(acc[mt][nt], ah[mt], bl);
                    mma_bf16(acc[mt][nt], al[mt], bh);
                }
            }
        }
        __syncthreads();
    }

    int grp = lane >> 2, qc = (lane & 3) << 1;
#pragma unroll
    for (int mt = 0; mt < 2; mt++) {
#pragma unroll
        for (int nt = 0; nt < 8; nt++) {
            int col = wn * 64 + nt * 8 + qc;
            float b0 = bias ? bias[col] : 0.f;
            float b1 = bias ? bias[col + 1] : 0.f;
#pragma unroll
            for (int hrow = 0; hrow < 2; hrow++) {
                int row = bm + wm * 32 + mt * 16 + grp + hrow * 8;
                if (row < M) {
                    float v0 = acc[mt][nt][hrow * 2 + 0] + b0;
                    float v1 = acc[mt][nt][hrow * 2 + 1] + b1;
                    if (doRelu) { v0 = fmaxf(v0, 0.f); v1 = fmaxf(v1, 0.f); }
                    if (gsum) {
                        int g = gid[row];
                        atomicAdd(&gsum[g * HH + col], v0);
                        atomicAdd(&gsum[g * HH + col + 1], v1);
                    } else {
                        *(float2*)(out + (size_t)row * 128 + col) = make_float2(v0, v1);
                    }
                }
            }
        }
    }
}

// ---------------- fused prologue fill ----------------
__global__ void prologue_fill(int* din, int* dout, int* cursor,
                              float* bsum, float* bsq, float* gcnt, float* gsum) {
    int i = blockIdx.x * blockDim.x + threadIdx.x;
    int stride = gridDim.x * blockDim.x;
    for (int k = i; k < NN; k += stride) { din[k] = 0; dout[k] = 0; cursor[k] = 0; }
    for (int k = i; k < 1024; k += stride) { bsum[k] = 0.f; bsq[k] = 0.f; }
    for (int k = i; k < GG; k += stride) gcnt[k] = 0.f;
    for (int k = i; k < 2 * GG * HH; k += stride) gsum[k] = 0.f;
}

__global__ void degree_int(const int* __restrict__ src, const int* __restrict__ dst,
                           int* dout, int* din, int E) {
    int e = blockIdx.x * blockDim.x + threadIdx.x;
    if (e < E) {
        atomicAdd(&dout[src[e]], 1);
        atomicAdd(&din[dst[e]], 1);
    }
}

// norms + normd + per-graph node counts in one pass
__global__ void make_norm2(const int* __restrict__ dout, const int* __restrict__ din,
                           const int* __restrict__ gid,
                           float* __restrict__ norms, float* __restrict__ normd,
                           float* __restrict__ gcnt, int n) {
    int i = blockIdx.x * blockDim.x + threadIdx.x;
    if (i < n) {
        norms[i] = rsqrtf(fmaxf((float)dout[i], 1.f));
        normd[i] = rsqrtf(fmaxf((float)din[i], 1.f));
        atomicAdd(&gcnt[gid[i]], 1.f);
    }
}

__global__ void scan_rowptr(const int* __restrict__ cnt, int* __restrict__ rowptr, int n) {
    __shared__ int wsum[32];
    __shared__ int carry;
    int tid = threadIdx.x, lane = tid & 31, wid = tid >> 5;
    if (tid == 0) carry = 0;
    __syncthreads();
    for (int base = 0; base < n; base += 1024) {
        int v = (base + tid < n) ? cnt[base + tid] : 0;
        int inc = v;
#pragma unroll
        for (int off = 1; off < 32; off <<= 1) {
            int t = __shfl_up_sync(0xffffffffu, inc, off);
            if (lane >= off) inc += t;
        }
        if (lane == 31) wsum[wid] = inc;
        __syncthreads();
        if (wid == 0) {
            int s = wsum[lane];
            int si = s;
#pragma unroll
            for (int off = 1; off < 32; off <<= 1) {
                int t = __shfl_up_sync(0xffffffffu, si, off);
                if (lane >= off) si += t;
            }
            wsum[lane] = si - s;
        }
        __syncthreads();
        int excl = carry + wsum[wid] + inc - v;
        if (base + tid < n) rowptr[base + tid] = excl;
        __syncthreads();
        if (tid == 1023) carry = excl + v;
        __syncthreads();
    }
    if (threadIdx.x == 0) rowptr[n] = carry;
}

__global__ void build_eidx(const int* __restrict__ dst, const int* __restrict__ src,
                           const int* __restrict__ et, const int* __restrict__ rowptr,
                           int* __restrict__ cursor, int* __restrict__ eidx,
                           int* __restrict__ gsrc, int* __restrict__ gett,
                           int* __restrict__ pos, int E) {
    int e = blockIdx.x * blockDim.x + threadIdx.x;
    if (e < E) {
        int d = dst[e];
        int p = rowptr[d] + atomicAdd(&cursor[d], 1);
        eidx[p] = e;
        gsrc[p] = src[e];
        gett[p] = et[e];
        pos[e] = p;
    }
}

__global__ void build_wcat(const float* __restrict__ Wrel, const float* __restrict__ Wself,
                           float* __restrict__ Wcat) {
    int i = blockIdx.x * blockDim.x + threadIdx.x;
    if (i < RR * HH * HH) Wcat[i] = Wrel[i];
    else if (i < KCAT * HH) Wcat[i] = Wself[i - RR * HH * HH];
}

// ---------------- BatchNorm stats (into caller-chosen slot; prologue pre-zeroed) ----------------
__global__ void bn_stats(const float* __restrict__ X, int M,
                         float* sum, float* sumsq) {
    int j = threadIdx.x;  // 128
    float s = 0.f, s2 = 0.f;
    for (int m = blockIdx.x; m < M; m += gridDim.x) {
        float v = X[(size_t)m * HH + j];
        s += v; s2 += v * v;
    }
    atomicAdd(&sum[j], s);
    atomicAdd(&sumsq[j], s2);
}

__global__ void bn_stats2(const float* __restrict__ X, const float* __restrict__ natt,
                          int M, float* sum, float* sumsq) {
    int j = threadIdx.x;  // 128
    float s0 = 0.f, q0 = 0.f, s1 = 0.f, q1 = 0.f;
    for (int m = blockIdx.x; m < M; m += gridDim.x) {
        float x = X[(size_t)m * HH + j];
        float na0 = natt[2 * m], na1 = natt[2 * m + 1];
        float v0 = x * na0, v1 = x * na1;
        s0 += v0; q0 += v0 * v0;
        s1 += v1; q1 += v1 * v1;
    }
    atomicAdd(&sum[j], s0);       atomicAdd(&sumsq[j], q0);
    atomicAdd(&sum[128 + j], s1); atomicAdd(&sumsq[128 + j], q1);
}

// ---------------- fused CSR aggregation (batch-4, BN coefs computed inline) -------------
__global__ void csr_rel_gather_bn(const float* __restrict__ X,
                                  const float* __restrict__ sum, const float* __restrict__ sumsq,
                                  float invM,
                                  const int* __restrict__ gsrc, const int* __restrict__ gett,
                                  const int* __restrict__ rowptr,
                                  float* __restrict__ S, int Nn) {
    int gw = (blockIdx.x * blockDim.x + threadIdx.x) >> 5;
    if (gw >= Nn) return;
    int c = (threadIdx.x & 31) << 2;
    float4 sc, sh;
    bn_coef4(sum, sumsq, c, invM, sc, sh);
    float4 a0 = make_float4(0, 0, 0, 0), a1 = a0, a2 = a0, a3 = a0, a4 = a0;
    int j0 = rowptr[gw], j1 = rowptr[gw + 1];
    int j = j0;
#define RELACC(xx, rr)                                                        \
    {                                                                         \
        float4 v;                                                             \
        v.x = fmaf(xx.x, sc.x, sh.x); v.y = fmaf(xx.y, sc.y, sh.y);           \
        v.z = fmaf(xx.z, sc.z, sh.z); v.w = fmaf(xx.w, sc.w, sh.w);           \
        if (rr == 0)      { a0.x += v.x; a0.y += v.y; a0.z += v.z; a0.w += v.w; } \
        else if (rr == 1) { a1.x += v.x; a1.y += v.y; a1.z += v.z; a1.w += v.w; } \
        else if (rr == 2) { a2.x += v.x; a2.y += v.y; a2.z += v.z; a2.w += v.w; } \
        else if (rr == 3) { a3.x += v.x; a3.y += v.y; a3.z += v.z; a3.w += v.w; } \
        else              { a4.x += v.x; a4.y += v.y; a4.z += v.z; a4.w += v.w; } \
    }
    for (; j + 3 < j1; j += 4) {
        int s0 = gsrc[j], s1 = gsrc[j + 1], s2 = gsrc[j + 2], s3 = gsrc[j + 3];
        int r0 = gett[j], r1 = gett[j + 1], r2 = gett[j + 2], r3 = gett[j + 3];
        float4 x0 = *(const float4*)(X + (size_t)s0 * HH + c);
        float4 x1 = *(const float4*)(X + (size_t)s1 * HH + c);
        float4 x2 = *(const float4*)(X + (size_t)s2 * HH + c);
        float4 x3 = *(const float4*)(X + (size_t)s3 * HH + c);
        RELACC(x0, r0) RELACC(x1, r1) RELACC(x2, r2) RELACC(x3, r3)
    }
    for (; j < j1; j++) {
        int s = gsrc[j];
        int r = gett[j];
        float4 x = *(const float4*)(X + (size_t)s * HH + c);
        RELACC(x, r)
    }
#undef RELACC
    float4 xs = *(const float4*)(X + (size_t)gw * HH + c);
    float4 sv;
    sv.x = fmaf(xs.x, sc.x, sh.x); sv.y = fmaf(xs.y, sc.y, sh.y);
    sv.z = fmaf(xs.z, sc.z, sh.z); sv.w = fmaf(xs.w, sc.w, sh.w);
    float* Sp = S + (size_t)gw * KCAT + c;
    *(float4*)(Sp + 0)   = a0;
    *(float4*)(Sp + 128) = a1;
    *(float4*)(Sp + 256) = a2;
    *(float4*)(Sp + 384) = a3;
    *(float4*)(Sp + 512) = a4;
    *(float4*)(Sp + 640) = sv;
}

__global__ void csr_gather_bn(const float* __restrict__ X,
                              const float* __restrict__ sum, const float* __restrict__ sumsq,
                              float invM,
                              const float* __restrict__ norms,
                              const int* __restrict__ gsrc, const int* __restrict__ rowptr,
                              const float* __restrict__ normd, float* __restrict__ out, int Nn) {
    int gw = (blockIdx.x * blockDim.x + threadIdx.x) >> 5;
    if (gw >= Nn) return;
    int c = (threadIdx.x & 31) << 2;
    float4 sc, sh;
    bn_coef4(sum, sumsq, c, invM, sc, sh);
    float ax = 0.f, ay = 0.f, az = 0.f, aw = 0.f;
    int j0 = rowptr[gw], j1 = rowptr[gw + 1];
    int j = j0;
#define GACC(xx, nn)                                  \
    {                                                 \
        ax += fmaf(xx.x, sc.x, sh.x) * nn;            \
        ay += fmaf(xx.y, sc.y, sh.y) * nn;            \
        az += fmaf(xx.z, sc.z, sh.z) * nn;            \
        aw += fmaf(xx.w, sc.w, sh.w) * nn;            \
    }
    for (; j + 3 < j1; j += 4) {
        int s0 = gsrc[j], s1 = gsrc[j + 1], s2 = gsrc[j + 2], s3 = gsrc[j + 3];
        float n0 = norms[s0], n1 = norms[s1], n2 = norms[s2], n3 = norms[s3];
        float4 x0 = *(const float4*)(X + (size_t)s0 * HH + c);
        float4 x1 = *(const float4*)(X + (size_t)s1 * HH + c);
        float4 x2 = *(const float4*)(X + (size_t)s2 * HH + c);
        float4 x3 = *(const float4*)(X + (size_t)s3 * HH + c);
        GACC(x0, n0) GACC(x1, n1) GACC(x2, n2) GACC(x3, n3)
    }
    for (; j < j1; j++) {
        int s = gsrc[j];
        float ns = norms[s];
        float4 x = *(const float4*)(X + (size_t)s * HH + c);
        GACC(x, ns)
    }
#undef GACC
    float nd = normd[gw];
    *(float4*)(out + (size_t)gw * HH + c) = make_float4(ax * nd, ay * nd, az * nd, aw * nd);
}

__global__ void csr_gather_bn2(const float* __restrict__ X, const float* __restrict__ natt,
                               const float* __restrict__ sum, const float* __restrict__ sumsq,
                               float invM,
                               const float* __restrict__ norms,
                               const int* __restrict__ gsrc, const int* __restrict__ rowptr,
                               const float* __restrict__ geatt,
                               const float* __restrict__ normd,
                               float* __restrict__ outc, float* __restrict__ outs, int Nn) {
    int gw = (blockIdx.x * blockDim.x + threadIdx.x) >> 5;
    if (gw >= Nn) return;
    int c = (threadIdx.x & 31) << 2;
    float4 sc0, sh0, sc1, sh1;
    bn_coef4(sum, sumsq, c, invM, sc0, sh0);
    bn_coef4(sum, sumsq, 128 + c, invM, sc1, sh1);
    float cx = 0.f, cy = 0.f, cz = 0.f, cw = 0.f;
    float sx = 0.f, sy = 0.f, sz = 0.f, sw = 0.f;
    int j0 = rowptr[gw], j1 = rowptr[gw + 1];
    int j = j0;
#define BACC(xx, nat, nn, ww)                                         \
    {                                                                 \
        float f0 = nat.x * nn, f1 = nat.y * nn;                       \
        cx += ww.x * fmaf(xx.x, sc0.x * f0, sh0.x * nn);              \
        cy += ww.x * fmaf(xx.y, sc0.y * f0, sh0.y * nn);              \
        cz += ww.x * fmaf(xx.z, sc0.z * f0, sh0.z * nn);              \
        cw += ww.x * fmaf(xx.w, sc0.w * f0, sh0.w * nn);              \
        sx += ww.y * fmaf(xx.x, sc1.x * f1, sh1.x * nn);              \
        sy += ww.y * fmaf(xx.y, sc1.y * f1, sh1.y * nn);              \
        sz += ww.y * fmaf(xx.z, sc1.z * f1, sh1.z * nn);              \
        sw += ww.y * fmaf(xx.w, sc1.w * f1, sh1.w * nn);              \
    }
    for (; j + 3 < j1; j += 4) {
        int s0 = gsrc[j], s1 = gsrc[j + 1], s2 = gsrc[j + 2], s3 = gsrc[j + 3];
        float2 w0 = *(const float2*)(geatt + 2 * j);
        float2 w1 = *(const float2*)(geatt + 2 * (j + 1));
        float2 w2 = *(const float2*)(geatt + 2 * (j + 2));
        float2 w3 = *(const float2*)(geatt + 2 * (j + 3));
        float n0 = norms[s0], n1 = norms[s1], n2 = norms[s2], n3 = norms[s3];
        float2 t0 = *(const float2*)(natt + 2 * s0);
        float2 t1 = *(const float2*)(natt + 2 * s1);
        float2 t2 = *(const float2*)(natt + 2 * s2);
        float2 t3 = *(const float2*)(natt + 2 * s3);
        float4 x0 = *(const float4*)(X + (size_t)s0 * HH + c);
        float4 x1 = *(const float4*)(X + (size_t)s1 * HH + c);
        float4 x2 = *(const float4*)(X + (size_t)s2 * HH + c);
        float4 x3 = *(const float4*)(X + (size_t)s3 * HH + c);
        BACC(x0, t0, n0, w0) BACC(x1, t1, n1, w1)
        BACC(x2, t2, n2, w2) BACC(x3, t3, n3, w3)
    }
    for (; j < j1; j++) {
        int s = gsrc[j];
        float2 w = *(const float2*)(geatt + 2 * j);
        float ns = norms[s];
        float2 t = *(const float2*)(natt + 2 * s);
        float4 x = *(const float4*)(X + (size_t)s * HH + c);
        BACC(x, t, ns, w)
    }
#undef BACC
    float nd = normd[gw];
    *(float4*)(outc + (size_t)gw * HH + c) = make_float4(cx * nd, cy * nd, cz * nd, cw * nd);
    *(float4*)(outs + (size_t)gw * HH + c) = make_float4(sx * nd, sy * nd, sz * nd, sw * nd);
}

// ---------------- attention kernels ----------------
__global__ void node_att_kernel(const float* __restrict__ x, const float* __restrict__ W,
                                const float* __restrict__ b, float* __restrict__ natt, int Nn) {
    __shared__ float Ws[256];
    for (int i = threadIdx.x; i < 256; i += blockDim.x) Ws[i] = W[i];
    __syncthreads();
    int gi = blockIdx.x * blockDim.x + threadIdx.x;
    int n = gi >> 5, lane = threadIdx.x & 31;
    if (n >= Nn) return;
    float4 xv = *(const float4*)(x + (size_t)n * HH + (lane << 2));
    float vv[4] = {xv.x, xv.y, xv.z, xv.w};
    float s0 = 0.f, s1 = 0.f;
#pragma unroll
    for (int t = 0; t < 4; t++) {
        int k = (lane << 2) + t;
        s0 = fmaf(vv[t], Ws[k * 2 + 0], s0);
        s1 = fmaf(vv[t], Ws[k * 2 + 1], s1);
    }
    for (int o = 16; o > 0; o >>= 1) {
        s0 += __shfl_down_sync(0xffffffffu, s0, o);
        s1 += __shfl_down_sync(0xffffffffu, s1, o);
    }
    if (lane == 0) {
        float z0 = s0 + b[0], z1 = s1 + b[1];
        float m = fmaxf(z0, z1);
        float e0 = expf(z0 - m), e1 = expf(z1 - m);
        float inv = 1.f / (e0 + e1);
        natt[(size_t)n * 2 + 0] = e0 * inv;
        natt[(size_t)n * 2 + 1] = e1 * inv;
    }
}

__global__ void edge_att_kernel(const float* __restrict__ x, const int* __restrict__ src,
                                const int* __restrict__ dst, const float* __restrict__ W,
                                const float* __restrict__ b, const int* __restrict__ pos,
                                float* __restrict__ eatt, float* __restrict__ geatt, int E) {
    __shared__ float Ws[512];
    for (int i = threadIdx.x; i < 512; i += blockDim.x) Ws[i] = W[i];
    __syncthreads();
    int gi = blockIdx.x * blockDim.x + threadIdx.x;
    int e = gi >> 5, lane = threadIdx.x & 31;
    if (e >= E) return;
    int s = src[e], d = dst[e];
    float4 xs = *(const float4*)(x + (size_t)s * HH + (lane << 2));
    float4 xd = *(const float4*)(x + (size_t)d * HH + (lane << 2));
    float vs[4] = {xs.x, xs.y, xs.z, xs.w};
    float vd[4] = {xd.x, xd.y, xd.z, xd.w};
    float s0 = 0.f, s1 = 0.f;
#pragma unroll
    for (int t = 0; t < 4; t++) {
        int k = (lane << 2) + t;
        s0 = fmaf(vs[t], Ws[k * 2 + 0], s0);
        s1 = fmaf(vs[t], Ws[k * 2 + 1], s1);
        s0 = fmaf(vd[t], Ws[(128 + k) * 2 + 0], s0);
        s1 = fmaf(vd[t], Ws[(128 + k) * 2 + 1], s1);
    }
    for (int o = 16; o > 0; o >>= 1) {
        s0 += __shfl_down_sync(0xffffffffu, s0, o);
        s1 += __shfl_down_sync(0xffffffffu, s1, o);
    }
    if (lane == 0) {
        float z0 = s0 + b[0], z1 = s1 + b[1];
        float m = fmaxf(z0, z1);
        float e0 = expf(z0 - m), e1 = expf(z1 - m);
        float inv = 1.f / (e0 + e1);
        float w0 = e0 * inv, w1 = e1 * inv;
        eatt[(size_t)e * 2 + 0] = w0;
        eatt[(size_t)e * 2 + 1] = w1;
        int p = pos[e];
        geatt[(size_t)p * 2 + 0] = w0;
        geatt[(size_t)p * 2 + 1] = w1;
    }
}

// ---------------- per-graph mean (both branches, one launch) ----------------
__global__ void graph_div2(const float* gsum, const float* gcnt,
                           float* xcg, float* xsg, float* oc, float* os) {
    int i = blockIdx.x * blockDim.x + threadIdx.x;
    if (i >= GG * HH) return;
    int g = i / HH;
    float inv = 1.f / fmaxf(gcnt[g], 1.f);
    float v = gsum[i] * inv;
    float w = gsum[GG * HH + i] * inv;
    xcg[i] = v; oc[i] = v;
    xsg[i] = w; os[i] = w;
}

// ---------------- fused heads (single block) ----------------
__device__ __forceinline__ void threefry2x32(uint32_t k0, uint32_t k1, uint32_t x0, uint32_t x1,
                                             uint32_t* o0, uint32_t* o1) {
    uint32_t ks[3] = {k0, k1, k0 ^ k1 ^ 0x1BD11BDAu};
    const int r1[4] = {13, 15, 26, 6};
    const int r2[4] = {17, 29, 16, 24};
    x0 += ks[0]; x1 += ks[1];
#pragma unroll
    for (int i = 0; i < 5; i++) {
        const int* rot = (i % 2 == 0) ? r1 : r2;
#pragma unroll
        for (int j = 0; j < 4; j++) {
            x0 += x1;
            x1 = (x1 << rot[j]) | (x1 >> (32 - rot[j]));
            x1 ^= x0;
        }
        x0 += ks[(i + 1) % 3];
        x1 += ks[(i + 2) % 3] + (uint32_t)(i + 1);
    }
    *o0 = x0; *o1 = x1;
}

__device__ void blk_bn(const float* in, float* out, int K) {
    int j = threadIdx.x;
    if (j < K) {
        float s = 0.f, s2 = 0.f;
        for (int m = 0; m < GG; m++) {
            float v = in[m * K + j];
            s += v; s2 += v * v;
        }
        float mean = s / GG;
        float var = s2 / GG - mean * mean;
        float r = rsqrtf(var + EPSF);
        for (int m = 0; m < GG; m++)
            out[m * K + j] = (in[m * K + j] - mean) * r + BETAF;
    }
    __syncthreads();
}

__device__ void blk_fc(const float* A, const float* W, const float* b, float* C,
                       int Kin, int Kout, int doRelu) {
    for (int i = threadIdx.x; i < GG * Kout; i += blockDim.x) {
        int m = i / Kout, j = i - m * Kout;
        float s = b ? b[j] : 0.f;
        for (int k = 0; k < Kin; k++) s = fmaf(A[m * Kin + k], W[k * Kout + j], s);
        C[i] = doRelu ? fmaxf(s, 0.f) : s;
    }
    __syncthreads();
}

__global__ void heads_kernel(
    const float* __restrict__ xcg, const float* __restrict__ xsg,
    const float* cfc1W, const float* cfc1b, const float* cfc2W, const float* cfc2b,
    const float* sfc1W, const float* sfc1b, const float* sfc2W, const float* sfc2b,
    const float* ccat1W, const float* ccat1b, const float* ccat2W, const float* ccat2b,
    float* h1, float* h2, float* h3, float* xcat,
    float* out_causal, float* out_spur, float* out_ctx) {
    __shared__ uint32_t keys[64];
    __shared__ int sperm[64];
    int tid = threadIdx.x;
    if (tid < 64) {
        uint32_t sk0, sk1, o0, o1;
        threefry2x32(0u, 42u, 0u, 1u, &sk0, &sk1);
        threefry2x32(sk0, sk1, 0u, (uint32_t)tid, &o0, &o1);
        keys[tid] = o0 ^ o1;
    }
    __syncthreads();
    if (tid < 64) {
        uint32_t ki = keys[tid];
        int rank = 0;
        for (int j = 0; j < 64; j++) {
            uint32_t kj = keys[j];
            rank += (kj < ki) || (kj == ki && j < tid);
        }
        sperm[rank] = tid;
    }
    __syncthreads();

    // causal head
    blk_bn(xcg, h1, 128);
    blk_fc(h1, cfc1W, cfc1b, h2, 128, DD, 1);
    blk_bn(h2, h3, DD);
    blk_fc(h3, cfc2W, cfc2b, out_causal, DD, CCH, 0);

    // spurious head
    blk_bn(xsg, h1, 128);
    blk_fc(h1, sfc1W, sfc1b, h2, 128, DD, 1);
    blk_bn(h2, h3, DD);
    blk_fc(h3, sfc2W, sfc2b, h2, DD, CCH, 0);
    if (tid < GG) {
        float z0 = h2[tid * 2], z1 = h2[tid * 2 + 1];
        float m = fmaxf(z0, z1);
        float l = m + logf(expf(z0 - m) + expf(z1 - m));
        out_spur[tid * 2] = z0 - l;
        out_spur[tid * 2 + 1] = z1 - l;
    }
    __syncthreads();

    // context head
    for (int i = tid; i < GG * 256; i += blockDim.x) {
        int g = i >> 8, c = i & 255;
        xcat[i] = (c < HH) ? xcg[g * HH + c] : xsg[sperm[g] * HH + (c - HH)];
    }
    __syncthreads();
    blk_bn(xcat, h1, 256);
    blk_fc(h1, ccat1W, ccat1b, h2, 256, DD, 1);
    blk_bn(h2, h3, DD);
    blk_fc(h3, ccat2W, ccat2b, out_ctx, DD, CCH, 0);
}

// ---------------- launch ----------------
extern "C" void kernel_launch(void* const* d_in, const int* in_sizes, int n_in,
                              void* d_out, int out_size) {
    const float* feat = nullptr;
    const int *src = nullptr, *dst = nullptr, *et = nullptr, *gid = nullptr;
    const float* Wp[27];
    int wi = 0, eseen = 0;
    for (int i = 0; i < n_in; i++) {
        int sz = in_sizes[i];
        if (sz == NN * BERTD) feat = (const float*)d_in[i];
        else if (sz == EE) {
            if (eseen == 0) src = (const int*)d_in[i];
            else if (eseen == 1) dst = (const int*)d_in[i];
            else et = (const int*)d_in[i];
            eseen++;
        } else if (sz == NN) gid = (const int*)d_in[i];
        else if (wi < 27) Wp[wi++] = (const float*)d_in[i];
    }
    const float *W_red = Wp[0], *b_red = Wp[1], *W_rel = Wp[2], *W_self = Wp[3], *b_rel = Wp[4];
    const float *W_conv = Wp[5], *b_conv = Wp[6], *W_eatt = Wp[7], *b_eatt = Wp[8];
    const float *W_natt = Wp[9], *b_natt = Wp[10], *W_cconv = Wp[11], *b_cconv = Wp[12];
    const float *W_sconv = Wp[13], *b_sconv = Wp[14];
    const float *cfc1W = Wp[15], *cfc1b = Wp[16], *cfc2W = Wp[17], *cfc2b = Wp[18];
    const float *sfc1W = Wp[19], *sfc1b = Wp[20], *sfc2W = Wp[21], *sfc2b = Wp[22];
    const float *ccat1W = Wp[23], *ccat1b = Wp[24], *ccat2W = Wp[25], *ccat2b = Wp[26];

    float *A, *B, *Cc, *S, *Wcat, *norms, *normd, *bsum, *bsq;
    float *gsum, *gcnt, *xcg, *xsg, *h1, *h2, *h3, *xcat, *geatt;
    int *din, *dout, *rowptr, *cursor, *eidx, *gsrc, *gett, *pos;
    cudaGetSymbolAddress((void**)&A, g_A);
    cudaGetSymbolAddress((void**)&B, g_B);
    cudaGetSymbolAddress((void**)&Cc, g_Cacc);
    cudaGetSymbolAddress((void**)&S, g_S);
    cudaGetSymbolAddress((void**)&Wcat, g_Wcat);
    cudaGetSymbolAddress((void**)&norms, g_norms);
    cudaGetSymbolAddress((void**)&normd, g_normd);
    cudaGetSymbolAddress((void**)&din, g_din);
    cudaGetSymbolAddress((void**)&dout, g_dout);
    cudaGetSymbolAddress((void**)&rowptr, g_rowptr);
    cudaGetSymbolAddress((void**)&cursor, g_cursor);
    cudaGetSymbolAddress((void**)&eidx, g_eidx);
    cudaGetSymbolAddress((void**)&gsrc, g_gsrc);
    cudaGetSymbolAddress((void**)&gett, g_gett);
    cudaGetSymbolAddress((void**)&pos, g_pos);
    cudaGetSymbolAddress((void**)&geatt, g_geatt);
    cudaGetSymbolAddress((void**)&bsum, g_sum);
    cudaGetSymbolAddress((void**)&bsq, g_sumsq);
    cudaGetSymbolAddress((void**)&gsum, g_gsum);
    cudaGetSymbolAddress((void**)&gcnt, g_gcnt);
    cudaGetSymbolAddress((void**)&xcg, g_xcg);
    cudaGetSymbolAddress((void**)&xsg, g_xsg);
    cudaGetSymbolAddress((void**)&h1, g_h1);
    cudaGetSymbolAddress((void**)&h2, g_h2);
    cudaGetSymbolAddress((void**)&h3, g_h3);
    cudaGetSymbolAddress((void**)&xcat, g_xcat);

    float* out = (float*)d_out;
    float* out_causal = out;
    float* out_spur = out + GG * CCH;
    float* out_ctx = out + 2 * GG * CCH;
    float* out_xcg = out + 3 * GG * CCH;
    float* out_xsg = out_xcg + GG * HH;
    float* out_natt = out_xsg + GG * HH;
    float* out_eatt = out_natt + NN * 2;

    const int gemmGrid = (NN + 127) / 128;
    const int edgeWGrid = (EE * 32 + 255) / 256;
    const int nodeWGrid = (NN * 32 + 255) / 256;
    const int gatherGrid = (NN + 7) / 8;
    const float invM = 1.f / NN;

    // one fused prologue fill
    prologue_fill<<<256, 256>>>(din, dout, cursor, bsum, bsq, gcnt, gsum);

    // feat reduce GEMM
    tgemm<<<gemmGrid, 256>>>(feat, W_red, b_red, A, NN, BERTD, 0, nullptr, nullptr,
                             nullptr, nullptr, nullptr, nullptr, 0);

    // CSR build + degree norms + graph counts
    degree_int<<<(EE + 255) / 256, 256>>>(src, dst, dout, din, EE);
    make_norm2<<<(NN + 255) / 256, 256>>>(dout, din, gid, norms, normd, gcnt, NN);
    scan_rowptr<<<1, 1024>>>(din, rowptr, NN);
    build_eidx<<<(EE + 255) / 256, 256>>>(dst, src, et, rowptr, cursor, eidx, gsrc, gett, pos, EE);
    build_wcat<<<(KCAT * HH + 255) / 256, 256>>>(W_rel, W_self, Wcat);

    // feat BN stats (slot 0)
    bn_stats<<<512, 128>>>(A, NN, bsum, bsq);

    // RelGraphConv (aggregate-first, BN coefs inline from slot 0)
    csr_rel_gather_bn<<<gatherGrid, 256>>>(A, bsum, bsq, invM, gsrc, gett, rowptr, S, NN);
    tgemm<<<gemmGrid, 256>>>(S, Wcat, b_rel, A, NN, KCAT, 1, nullptr, nullptr,
                             nullptr, nullptr, nullptr, nullptr, 0);

    // two GraphConv layers (stats slots 1, 2)
    for (int i = 0; i < 2; i++) {
        float* ss = bsum + 128 * (i + 1);
        float* qq = bsq + 128 * (i + 1);
        bn_stats<<<512, 128>>>(A, NN, ss, qq);
        csr_gather_bn<<<gatherGrid, 256>>>(A, ss, qq, invM, norms, gsrc, rowptr, normd, Cc, NN);
        tgemm<<<gemmGrid, 256>>>(Cc, W_conv + (size_t)i * HH * HH, b_conv + i * HH, A, NN, HH, 1,
                                 nullptr, nullptr, nullptr, nullptr, nullptr, nullptr, 0);
    }

    // attentions
    node_att_kernel<<<nodeWGrid, 256>>>(A, W_natt, b_natt, out_natt, NN);
    edge_att_kernel<<<edgeWGrid, 256>>>(A, src, dst, W_eatt, b_eatt, pos, out_eatt, geatt, EE);

    // both branches: stats (slot at 384, 256-wide) + one fused gather pass
    bn_stats2<<<512, 128>>>(A, out_natt, NN, bsum + 384, bsq + 384);
    csr_gather_bn2<<<gatherGrid, 256>>>(A, out_natt, bsum + 384, bsq + 384, invM,
                                        norms, gsrc, rowptr, geatt, normd, Cc, B, NN);

    // both branch GEMMs in ONE launch (fused pooling into gsum halves)
    tgemm<<<2 * gemmGrid, 256>>>(Cc, W_cconv, b_cconv, nullptr, NN, HH, 1, gid, gsum,
                                 B, W_sconv, b_sconv, gsum + GG * HH, gemmGrid);
    graph_div2<<<(GG * HH + 255) / 256, 256>>>(gsum, gcnt, xcg, xsg, out_xcg, out_xsg);

    // all three heads in one fused single-block kernel
    heads_kernel<<<1, 256>>>(xcg, xsg,
                             cfc1W, cfc1b, cfc2W, cfc2b,
                             sfc1W, sfc1b, sfc2W, sfc2b,
                             ccat1W, ccat1b, ccat2W, ccat2b,
                             h1, h2, h3, xcat,
                             out_causal, out_spur, out_ctx);
}

// round 17
// speedup vs baseline: 1.0746x; 1.0595x over previous
#include <cuda_runtime.h>
#include <cuda_bf16.h>
#include <math.h>
#include <stdint.h>

#define NN 50000
#define EE 800000
#define GG 64
#define RR 5
#define BERTD 768
#define HH 128
#define DD 32
#define CCH 2
#define EPSF 1e-5f
#define BETAF 1e-4f
#define KCAT 768   // 5*128 rel + 128 self

// ---------------- scratch (device globals; no allocation) ----------------
__device__ float g_A[NN * HH];
__device__ float g_B[NN * HH];
__device__ float g_Cacc[NN * HH];
__device__ float g_S[NN * KCAT];
__device__ float g_Wcat[KCAT * HH];
__device__ float g_norms[NN];
__device__ float g_normd[NN];
__device__ int g_din[NN];
__device__ int g_dout[NN];
__device__ int g_rowptr[NN + 1];
__device__ int g_cursor[NN];
__device__ int g_eidx[EE];
__device__ int g_gsrc[EE];
__device__ int g_gett[EE];
__device__ int g_pos[EE];
__device__ float g_geatt[EE * 2];
__device__ float g_sum[1024];     // stats slots: 0=feat,128=conv1,256=conv2,384..639=branch2
__device__ float g_sumsq[1024];
__device__ float g_gsum[2 * GG * HH];
__device__ float g_gcnt[GG];
__device__ float g_xcg[GG * HH];
__device__ float g_xsg[GG * HH];
__device__ float g_h1[GG * 256];
__device__ float g_h2[GG * 256];
__device__ float g_h3[GG * 256];
__device__ float g_xcat[GG * 256];

// ---------------- mma.sync helpers ----------------
__device__ __forceinline__ void ldsm_x4(uint32_t* r, uint32_t addr) {
    asm volatile("ldmatrix.sync.aligned.m8n8.x4.shared.b16 {%0,%1,%2,%3}, [%4];"
                 : "=r"(r[0]), "=r"(r[1]), "=r"(r[2]), "=r"(r[3]) : "r"(addr));
}
__device__ __forceinline__ void ldsm_x2t(uint32_t* r, uint32_t addr) {
    asm volatile("ldmatrix.sync.aligned.m8n8.x2.trans.shared.b16 {%0,%1}, [%2];"
                 : "=r"(r[0]), "=r"(r[1]) : "r"(addr));
}
__device__ __forceinline__ void mma_bf16(float* c, const uint32_t* a, const uint32_t* b) {
    asm volatile(
        "mma.sync.aligned.m16n8k16.row.col.f32.bf16.bf16.f32 "
        "{%0,%1,%2,%3}, {%4,%5,%6,%7}, {%8,%9}, {%0,%1,%2,%3};"
        : "+f"(c[0]), "+f"(c[1]), "+f"(c[2]), "+f"(c[3])
        : "r"(a[0]), "r"(a[1]), "r"(a[2]), "r"(a[3]), "r"(b[0]), "r"(b[1]));
}
__device__ __forceinline__ void split_bf16(float x, __nv_bfloat16& h, __nv_bfloat16& l) {
    h = __float2bfloat16_rn(x);
    l = __float2bfloat16_rn(x - __bfloat162float(h));
}
__device__ __forceinline__ void bn_coef4(const float* sum, const float* sumsq, int c,
                                         float invM, float4& sc, float4& sh) {
    float4 s4 = *(const float4*)(sum + c);
    float4 q4 = *(const float4*)(sumsq + c);
    float m0 = s4.x * invM, m1 = s4.y * invM, m2 = s4.z * invM, m3 = s4.w * invM;
    sc.x = rsqrtf(q4.x * invM - m0 * m0 + EPSF);
    sc.y = rsqrtf(q4.y * invM - m1 * m1 + EPSF);
    sc.z = rsqrtf(q4.z * invM - m2 * m2 + EPSF);
    sc.w = rsqrtf(q4.w * invM - m3 * m3 + EPSF);
    sh.x = BETAF - m0 * sc.x; sh.y = BETAF - m1 * sc.y;
    sh.z = BETAF - m2 * sc.z; sh.w = BETAF - m3 * sc.w;
}

// ---------------- tensor-core GEMM via mma.sync (bf16x3 split) ----------------
#define PA 40
#define PB 136
__global__ void __launch_bounds__(256) tgemm(
    const float* __restrict__ A, const float* __restrict__ W,
    const float* __restrict__ bias, float* __restrict__ out,
    int M, int Kin, int doRelu,
    const int* __restrict__ gid, float* __restrict__ gsum,
    const float* __restrict__ A2, const float* __restrict__ W2,
    const float* __restrict__ bias2, float* __restrict__ gsum2, int gridHalf) {
    __shared__ __align__(16) __nv_bfloat16 sAh[128 * PA];
    __shared__ __align__(16) __nv_bfloat16 sAl[128 * PA];
    __shared__ __align__(16) __nv_bfloat16 sBh[32 * PB];
    __shared__ __align__(16) __nv_bfloat16 sBl[32 * PB];
    int tid = threadIdx.x, wid = tid >> 5, lane = tid & 31;
    int bx = blockIdx.x;
    if (gridHalf && bx >= gridHalf) {
        A = A2; W = W2; bias = bias2; gsum = gsum2;
        bx -= gridHalf;
    }
    int bm = bx * 128;
    int wm = wid & 3, wn = wid >> 2;

    float acc[2][8][4];
#pragma unroll
    for (int i = 0; i < 2; i++)
#pragma unroll
        for (int j = 0; j < 8; j++)
#pragma unroll
            for (int t = 0; t < 4; t++) acc[i][j][t] = 0.f;

    for (int kc = 0; kc < Kin; kc += 32) {
#pragma unroll
        for (int i = 0; i < 4; i++) {
            int idx = tid + i * 256;
            int row = idx >> 3;
            int c4 = idx & 7;
            int grow = bm + row;
            float4 v = make_float4(0.f, 0.f, 0.f, 0.f);
            if (grow < M) v = *(const float4*)(A + (size_t)grow * Kin + kc + (c4 << 2));
            __nv_bfloat16 h0, h1, h2, h3, l0, l1, l2, l3;
            split_bf16(v.x, h0, l0); split_bf16(v.y, h1, l1);
            split_bf16(v.z, h2, l2); split_bf16(v.w, h3, l3);
            __nv_bfloat162 hA = __halves2bfloat162(h0, h1), hB = __halves2bfloat162(h2, h3);
            __nv_bfloat162 lA = __halves2bfloat162(l0, l1), lB = __halves2bfloat162(l2, l3);
            int off = row * PA + (c4 << 2);
            *(uint2*)&sAh[off] = make_uint2(*(uint32_t*)&hA, *(uint32_t*)&hB);
            *(uint2*)&sAl[off] = make_uint2(*(uint32_t*)&lA, *(uint32_t*)&lB);
        }
#pragma unroll
        for (int i = 0; i < 4; i++) {
            int idx = tid + i * 256;
            int row = idx >> 5;
            int c4 = idx & 31;
            float4 v = *(const float4*)(W + (size_t)(kc + row) * 128 + (c4 << 2));
            __nv_bfloat16 h0, h1, h2, h3, l0, l1, l2, l3;
            split_bf16(v.x, h0, l0); split_bf16(v.y, h1, l1);
            split_bf16(v.z, h2, l2); split_bf16(v.w, h3, l3);
            __nv_bfloat162 hA = __halves2bfloat162(h0, h1), hB = __halves2bfloat162(h2, h3);
            __nv_bfloat162 lA = __halves2bfloat162(l0, l1), lB = __halves2bfloat162(l2, l3);
            int off = row * PB + (c4 << 2);
            *(uint2*)&sBh[off] = make_uint2(*(uint32_t*)&hA, *(uint32_t*)&hB);
            *(uint2*)&sBl[off] = make_uint2(*(uint32_t*)&lA, *(uint32_t*)&lB);
        }
        __syncthreads();

#pragma unroll
        for (int ks = 0; ks < 2; ks++) {
            int k0 = ks << 4;
            uint32_t ah[2][4], al[2][4];
            int t4 = lane >> 3, r8 = lane & 7;
            int arow_off = (t4 & 1) * 8 + r8;
            int acol_off = (t4 >> 1) * 8;
#pragma unroll
            for (int mt = 0; mt < 2; mt++) {
                int m0 = wm * 32 + mt * 16;
                int aoff = (m0 + arow_off) * PA + k0 + acol_off;
                ldsm_x4(ah[mt], (uint32_t)__cvta_generic_to_shared(&sAh[aoff]));
                ldsm_x4(al[mt], (uint32_t)__cvta_generic_to_shared(&sAl[aoff]));
            }
            int bt = (lane >> 3) & 1;
#pragma unroll
            for (int nt = 0; nt < 8; nt++) {
                int n0 = wn * 64 + nt * 8;
                int boff = (k0 + bt * 8 + r8) * PB + n0;
                uint32_t bh[2], bl[2];
                ldsm_x2t(bh, (uint32_t)__cvta_generic_to_shared(&sBh[boff]));
                ldsm_x2t(bl, (uint32_t)__cvta_generic_to_shared(&sBl[boff]));
#pragma unroll
                for (int mt = 0; mt < 2; mt++) {
                    mma_bf16(acc[mt][nt], ah[mt], bh);
                    mma_bf16(acc[mt][nt], ah[mt], bl);
                    mma_bf16(acc[mt][nt], al[mt], bh);
                }
            }
        }
        __syncthreads();
    }

    int grp = lane >> 2, qc = (lane & 3) << 1;
#pragma unroll
    for (int mt = 0; mt < 2; mt++) {
#pragma unroll
        for (int nt = 0; nt < 8; nt++) {
            int col = wn * 64 + nt * 8 + qc;
            float b0 = bias ? bias[col] : 0.f;
            float b1 = bias ? bias[col + 1] : 0.f;
#pragma unroll
            for (int hrow = 0; hrow < 2; hrow++) {
                int row = bm + wm * 32 + mt * 16 + grp + hrow * 8;
                if (row < M) {
                    float v0 = acc[mt][nt][hrow * 2 + 0] + b0;
                    float v1 = acc[mt][nt][hrow * 2 + 1] + b1;
                    if (doRelu) { v0 = fmaxf(v0, 0.f); v1 = fmaxf(v1, 0.f); }
                    if (gsum) {
                        int g = gid[row];
                        atomicAdd(&gsum[g * HH + col], v0);
                        atomicAdd(&gsum[g * HH + col + 1], v1);
                    } else {
                        *(float2*)(out + (size_t)row * 128 + col) = make_float2(v0, v1);
                    }
                }
            }
        }
    }
}

// ---------------- fused prologue fill ----------------
__global__ void prologue_fill(int* din, int* dout, int* cursor,
                              float* bsum, float* bsq, float* gcnt, float* gsum) {
    int i = blockIdx.x * blockDim.x + threadIdx.x;
    int stride = gridDim.x * blockDim.x;
    for (int k = i; k < NN; k += stride) { din[k] = 0; dout[k] = 0; cursor[k] = 0; }
    for (int k = i; k < 1024; k += stride) { bsum[k] = 0.f; bsq[k] = 0.f; }
    for (int k = i; k < GG; k += stride) gcnt[k] = 0.f;
    for (int k = i; k < 2 * GG * HH; k += stride) gsum[k] = 0.f;
}

__global__ void degree_int(const int* __restrict__ src, const int* __restrict__ dst,
                           int* dout, int* din, int E) {
    int e = blockIdx.x * blockDim.x + threadIdx.x;
    if (e < E) {
        atomicAdd(&dout[src[e]], 1);
        atomicAdd(&din[dst[e]], 1);
    }
}

// norms + normd + per-graph node counts (smem-aggregated histogram)
__global__ void make_norm2(const int* __restrict__ dout, const int* __restrict__ din,
                           const int* __restrict__ gid,
                           float* __restrict__ norms, float* __restrict__ normd,
                           float* __restrict__ gcnt, int n) {
    __shared__ float hcnt[GG];
    if (threadIdx.x < GG) hcnt[threadIdx.x] = 0.f;
    __syncthreads();
    int i = blockIdx.x * blockDim.x + threadIdx.x;
    if (i < n) {
        norms[i] = rsqrtf(fmaxf((float)dout[i], 1.f));
        normd[i] = rsqrtf(fmaxf((float)din[i], 1.f));
        atomicAdd(&hcnt[gid[i]], 1.f);
    }
    __syncthreads();
    if (threadIdx.x < GG) {
        float v = hcnt[threadIdx.x];
        if (v != 0.f) atomicAdd(&gcnt[threadIdx.x], v);
    }
}

__global__ void scan_rowptr(const int* __restrict__ cnt, int* __restrict__ rowptr, int n) {
    __shared__ int wsum[32];
    __shared__ int carry;
    int tid = threadIdx.x, lane = tid & 31, wid = tid >> 5;
    if (tid == 0) carry = 0;
    __syncthreads();
    for (int base = 0; base < n; base += 1024) {
        int v = (base + tid < n) ? cnt[base + tid] : 0;
        int inc = v;
#pragma unroll
        for (int off = 1; off < 32; off <<= 1) {
            int t = __shfl_up_sync(0xffffffffu, inc, off);
            if (lane >= off) inc += t;
        }
        if (lane == 31) wsum[wid] = inc;
        __syncthreads();
        if (wid == 0) {
            int s = wsum[lane];
            int si = s;
#pragma unroll
            for (int off = 1; off < 32; off <<= 1) {
                int t = __shfl_up_sync(0xffffffffu, si, off);
                if (lane >= off) si += t;
            }
            wsum[lane] = si - s;
        }
        __syncthreads();
        int excl = carry + wsum[wid] + inc - v;
        if (base + tid < n) rowptr[base + tid] = excl;
        __syncthreads();
        if (tid == 1023) carry = excl + v;
        __syncthreads();
    }
    if (threadIdx.x == 0) rowptr[n] = carry;
}

__global__ void build_eidx(const int* __restrict__ dst, const int* __restrict__ src,
                           const int* __restrict__ et, const int* __restrict__ rowptr,
                           int* __restrict__ cursor, int* __restrict__ eidx,
                           int* __restrict__ gsrc, int* __restrict__ gett,
                           int* __restrict__ pos, int E) {
    int e = blockIdx.x * blockDim.x + threadIdx.x;
    if (e < E) {
        int d = dst[e];
        int p = rowptr[d] + atomicAdd(&cursor[d], 1);
        eidx[p] = e;
        gsrc[p] = src[e];
        gett[p] = et[e];
        pos[e] = p;
    }
}

__global__ void build_wcat(const float* __restrict__ Wrel, const float* __restrict__ Wself,
                           float* __restrict__ Wcat) {
    int i = blockIdx.x * blockDim.x + threadIdx.x;
    if (i < RR * HH * HH) Wcat[i] = Wrel[i];
    else if (i < KCAT * HH) Wcat[i] = Wself[i - RR * HH * HH];
}

// ---------------- BatchNorm stats ----------------
__global__ void bn_stats(const float* __restrict__ X, int M,
                         float* sum, float* sumsq) {
    int j = threadIdx.x;  // 128
    float s = 0.f, s2 = 0.f;
    for (int m = blockIdx.x; m < M; m += gridDim.x) {
        float v = X[(size_t)m * HH + j];
        s += v; s2 += v * v;
    }
    atomicAdd(&sum[j], s);
    atomicAdd(&sumsq[j], s2);
}

__global__ void bn_stats2(const float* __restrict__ X, const float* __restrict__ natt,
                          int M, float* sum, float* sumsq) {
    int j = threadIdx.x;  // 128
    float s0 = 0.f, q0 = 0.f, s1 = 0.f, q1 = 0.f;
    for (int m = blockIdx.x; m < M; m += gridDim.x) {
        float x = X[(size_t)m * HH + j];
        float na0 = natt[2 * m], na1 = natt[2 * m + 1];
        float v0 = x * na0, v1 = x * na1;
        s0 += v0; q0 += v0 * v0;
        s1 += v1; q1 += v1 * v1;
    }
    atomicAdd(&sum[j], s0);       atomicAdd(&sumsq[j], q0);
    atomicAdd(&sum[128 + j], s1); atomicAdd(&sumsq[128 + j], q1);
}

// ---------------- fused CSR aggregation (batch-4, BN coefs inline) -------------
__global__ void csr_rel_gather_bn(const float* __restrict__ X,
                                  const float* __restrict__ sum, const float* __restrict__ sumsq,
                                  float invM,
                                  const int* __restrict__ gsrc, const int* __restrict__ gett,
                                  const int* __restrict__ rowptr,
                                  float* __restrict__ S, int Nn) {
    int gw = (blockIdx.x * blockDim.x + threadIdx.x) >> 5;
    if (gw >= Nn) return;
    int c = (threadIdx.x & 31) << 2;
    float4 sc, sh;
    bn_coef4(sum, sumsq, c, invM, sc, sh);
    float4 a0 = make_float4(0, 0, 0, 0), a1 = a0, a2 = a0, a3 = a0, a4 = a0;
    int j0 = rowptr[gw], j1 = rowptr[gw + 1];
    int j = j0;
#define RELACC(xx, rr)                                                        \
    {                                                                         \
        float4 v;                                                             \
        v.x = fmaf(xx.x, sc.x, sh.x); v.y = fmaf(xx.y, sc.y, sh.y);           \
        v.z = fmaf(xx.z, sc.z, sh.z); v.w = fmaf(xx.w, sc.w, sh.w);           \
        if (rr == 0)      { a0.x += v.x; a0.y += v.y; a0.z += v.z; a0.w += v.w; } \
        else if (rr == 1) { a1.x += v.x; a1.y += v.y; a1.z += v.z; a1.w += v.w; } \
        else if (rr == 2) { a2.x += v.x; a2.y += v.y; a2.z += v.z; a2.w += v.w; } \
        else if (rr == 3) { a3.x += v.x; a3.y += v.y; a3.z += v.z; a3.w += v.w; } \
        else              { a4.x += v.x; a4.y += v.y; a4.z += v.z; a4.w += v.w; } \
    }
    for (; j + 3 < j1; j += 4) {
        int s0 = gsrc[j], s1 = gsrc[j + 1], s2 = gsrc[j + 2], s3 = gsrc[j + 3];
        int r0 = gett[j], r1 = gett[j + 1], r2 = gett[j + 2], r3 = gett[j + 3];
        float4 x0 = *(const float4*)(X + (size_t)s0 * HH + c);
        float4 x1 = *(const float4*)(X + (size_t)s1 * HH + c);
        float4 x2 = *(const float4*)(X + (size_t)s2 * HH + c);
        float4 x3 = *(const float4*)(X + (size_t)s3 * HH + c);
        RELACC(x0, r0) RELACC(x1, r1) RELACC(x2, r2) RELACC(x3, r3)
    }
    for (; j < j1; j++) {
        int s = gsrc[j];
        int r = gett[j];
        float4 x = *(const float4*)(X + (size_t)s * HH + c);
        RELACC(x, r)
    }
#undef RELACC
    float4 xs = *(const float4*)(X + (size_t)gw * HH + c);
    float4 sv;
    sv.x = fmaf(xs.x, sc.x, sh.x); sv.y = fmaf(xs.y, sc.y, sh.y);
    sv.z = fmaf(xs.z, sc.z, sh.z); sv.w = fmaf(xs.w, sc.w, sh.w);
    float* Sp = S + (size_t)gw * KCAT + c;
    *(float4*)(Sp + 0)   = a0;
    *(float4*)(Sp + 128) = a1;
    *(float4*)(Sp + 256) = a2;
    *(float4*)(Sp + 384) = a3;
    *(float4*)(Sp + 512) = a4;
    *(float4*)(Sp + 640) = sv;
}

__global__ void csr_gather_bn(const float* __restrict__ X,
                              const float* __restrict__ sum, const float* __restrict__ sumsq,
                              float invM,
                              const float* __restrict__ norms,
                              const int* __restrict__ gsrc, const int* __restrict__ rowptr,
                              const float* __restrict__ normd, float* __restrict__ out, int Nn) {
    int gw = (blockIdx.x * blockDim.x + threadIdx.x) >> 5;
    if (gw >= Nn) return;
    int c = (threadIdx.x & 31) << 2;
    float4 sc, sh;
    bn_coef4(sum, sumsq, c, invM, sc, sh);
    float ax = 0.f, ay = 0.f, az = 0.f, aw = 0.f;
    int j0 = rowptr[gw], j1 = rowptr[gw + 1];
    int j = j0;
#define GACC(xx, nn)                                  \
    {                                                 \
        ax += fmaf(xx.x, sc.x, sh.x) * nn;            \
        ay += fmaf(xx.y, sc.y, sh.y) * nn;            \
        az += fmaf(xx.z, sc.z, sh.z) * nn;            \
        aw += fmaf(xx.w, sc.w, sh.w) * nn;            \
    }
    for (; j + 3 < j1; j += 4) {
        int s0 = gsrc[j], s1 = gsrc[j + 1], s2 = gsrc[j + 2], s3 = gsrc[j + 3];
        float n0 = norms[s0], n1 = norms[s1], n2 = norms[s2], n3 = norms[s3];
        float4 x0 = *(const float4*)(X + (size_t)s0 * HH + c);
        float4 x1 = *(const float4*)(X + (size_t)s1 * HH + c);
        float4 x2 = *(const float4*)(X + (size_t)s2 * HH + c);
        float4 x3 = *(const float4*)(X + (size_t)s3 * HH + c);
        GACC(x0, n0) GACC(x1, n1) GACC(x2, n2) GACC(x3, n3)
    }
    for (; j < j1; j++) {
        int s = gsrc[j];
        float ns = norms[s];
        float4 x = *(const float4*)(X + (size_t)s * HH + c);
        GACC(x, ns)
    }
#undef GACC
    float nd = normd[gw];
    *(float4*)(out + (size_t)gw * HH + c) = make_float4(ax * nd, ay * nd, az * nd, aw * nd);
}

__global__ void csr_gather_bn2(const float* __restrict__ X, const float* __restrict__ natt,
                               const float* __restrict__ sum, const float* __restrict__ sumsq,
                               float invM,
                               const float* __restrict__ norms,
                               const int* __restrict__ gsrc, const int* __restrict__ rowptr,
                               const float* __restrict__ geatt,
                               const float* __restrict__ normd,
                               float* __restrict__ outc, float* __restrict__ outs, int Nn) {
    int gw = (blockIdx.x * blockDim.x + threadIdx.x) >> 5;
    if (gw >= Nn) return;
    int c = (threadIdx.x & 31) << 2;
    float4 sc0, sh0, sc1, sh1;
    bn_coef4(sum, sumsq, c, invM, sc0, sh0);
    bn_coef4(sum, sumsq, 128 + c, invM, sc1, sh1);
    float cx = 0.f, cy = 0.f, cz = 0.f, cw = 0.f;
    float sx = 0.f, sy = 0.f, sz = 0.f, sw = 0.f;
    int j0 = rowptr[gw], j1 = rowptr[gw + 1];
    int j = j0;
#define BACC(xx, nat, nn, ww)                                         \
    {                                                                 \
        float f0 = nat.x * nn, f1 = nat.y * nn;                       \
        cx += ww.x * fmaf(xx.x, sc0.x * f0, sh0.x * nn);              \
        cy += ww.x * fmaf(xx.y, sc0.y * f0, sh0.y * nn);              \
        cz += ww.x * fmaf(xx.z, sc0.z * f0, sh0.z * nn);              \
        cw += ww.x * fmaf(xx.w, sc0.w * f0, sh0.w * nn);              \
        sx += ww.y * fmaf(xx.x, sc1.x * f1, sh1.x * nn);              \
        sy += ww.y * fmaf(xx.y, sc1.y * f1, sh1.y * nn);              \
        sz += ww.y * fmaf(xx.z, sc1.z * f1, sh1.z * nn);              \
        sw += ww.y * fmaf(xx.w, sc1.w * f1, sh1.w * nn);              \
    }
    for (; j + 3 < j1; j += 4) {
        int s0 = gsrc[j], s1 = gsrc[j + 1], s2 = gsrc[j + 2], s3 = gsrc[j + 3];
        float2 w0 = *(const float2*)(geatt + 2 * j);
        float2 w1 = *(const float2*)(geatt + 2 * (j + 1));
        float2 w2 = *(const float2*)(geatt + 2 * (j + 2));
        float2 w3 = *(const float2*)(geatt + 2 * (j + 3));
        float n0 = norms[s0], n1 = norms[s1], n2 = norms[s2], n3 = norms[s3];
        float2 t0 = *(const float2*)(natt + 2 * s0);
        float2 t1 = *(const float2*)(natt + 2 * s1);
        float2 t2 = *(const float2*)(natt + 2 * s2);
        float2 t3 = *(const float2*)(natt + 2 * s3);
        float4 x0 = *(const float4*)(X + (size_t)s0 * HH + c);
        float4 x1 = *(const float4*)(X + (size_t)s1 * HH + c);
        float4 x2 = *(const float4*)(X + (size_t)s2 * HH + c);
        float4 x3 = *(const float4*)(X + (size_t)s3 * HH + c);
        BACC(x0, t0, n0, w0) BACC(x1, t1, n1, w1)
        BACC(x2, t2, n2, w2) BACC(x3, t3, n3, w3)
    }
    for (; j < j1; j++) {
        int s = gsrc[j];
        float2 w = *(const float2*)(geatt + 2 * j);
        float ns = norms[s];
        float2 t = *(const float2*)(natt + 2 * s);
        float4 x = *(const float4*)(X + (size_t)s * HH + c);
        BACC(x, t, ns, w)
    }
#undef BACC
    float nd = normd[gw];
    *(float4*)(outc + (size_t)gw * HH + c) = make_float4(cx * nd, cy * nd, cz * nd, cw * nd);
    *(float4*)(outs + (size_t)gw * HH + c) = make_float4(sx * nd, sy * nd, sz * nd, sw * nd);
}

// ---------------- attention kernels ----------------
__global__ void node_att_kernel(const float* __restrict__ x, const float* __restrict__ W,
                                const float* __restrict__ b, float* __restrict__ natt, int Nn) {
    __shared__ float Ws[256];
    for (int i = threadIdx.x; i < 256; i += blockDim.x) Ws[i] = W[i];
    __syncthreads();
    int gi = blockIdx.x * blockDim.x + threadIdx.x;
    int n = gi >> 5, lane = threadIdx.x & 31;
    if (n >= Nn) return;
    float4 xv = *(const float4*)(x + (size_t)n * HH + (lane << 2));
    float vv[4] = {xv.x, xv.y, xv.z, xv.w};
    float s0 = 0.f, s1 = 0.f;
#pragma unroll
    for (int t = 0; t < 4; t++) {
        int k = (lane << 2) + t;
        s0 = fmaf(vv[t], Ws[k * 2 + 0], s0);
        s1 = fmaf(vv[t], Ws[k * 2 + 1], s1);
    }
    for (int o = 16; o > 0; o >>= 1) {
        s0 += __shfl_down_sync(0xffffffffu, s0, o);
        s1 += __shfl_down_sync(0xffffffffu, s1, o);
    }
    if (lane == 0) {
        float z0 = s0 + b[0], z1 = s1 + b[1];
        float m = fmaxf(z0, z1);
        float e0 = expf(z0 - m), e1 = expf(z1 - m);
        float inv = 1.f / (e0 + e1);
        natt[(size_t)n * 2 + 0] = e0 * inv;
        natt[(size_t)n * 2 + 1] = e1 * inv;
    }
}

__global__ void edge_att_kernel(const float* __restrict__ x, const int* __restrict__ src,
                                const int* __restrict__ dst, const float* __restrict__ W,
                                const float* __restrict__ b, const int* __restrict__ pos,
                                float* __restrict__ eatt, float* __restrict__ geatt, int E) {
    __shared__ float Ws[512];
    for (int i = threadIdx.x; i < 512; i += blockDim.x) Ws[i] = W[i];
    __syncthreads();
    int gi = blockIdx.x * blockDim.x + threadIdx.x;
    int e = gi >> 5, lane = threadIdx.x & 31;
    if (e >= E) return;
    int s = src[e], d = dst[e];
    float4 xs = *(const float4*)(x + (size_t)s * HH + (lane << 2));
    float4 xd = *(const float4*)(x + (size_t)d * HH + (lane << 2));
    float vs[4] = {xs.x, xs.y, xs.z, xs.w};
    float vd[4] = {xd.x, xd.y, xd.z, xd.w};
    float s0 = 0.f, s1 = 0.f;
#pragma unroll
    for (int t = 0; t < 4; t++) {
        int k = (lane << 2) + t;
        s0 = fmaf(vs[t], Ws[k * 2 + 0], s0);
        s1 = fmaf(vs[t], Ws[k * 2 + 1], s1);
        s0 = fmaf(vd[t], Ws[(128 + k) * 2 + 0], s0);
        s1 = fmaf(vd[t], Ws[(128 + k) * 2 + 1], s1);
    }
    for (int o = 16; o > 0; o >>= 1) {
        s0 += __shfl_down_sync(0xffffffffu, s0, o);
        s1 += __shfl_down_sync(0xffffffffu, s1, o);
    }
    if (lane == 0) {
        float z0 = s0 + b[0], z1 = s1 + b[1];
        float m = fmaxf(z0, z1);
        float e0 = expf(z0 - m), e1 = expf(z1 - m);
        float inv = 1.f / (e0 + e1);
        float w0 = e0 * inv, w1 = e1 * inv;
        eatt[(size_t)e * 2 + 0] = w0;
        eatt[(size_t)e * 2 + 1] = w1;
        int p = pos[e];
        geatt[(size_t)p * 2 + 0] = w0;
        geatt[(size_t)p * 2 + 1] = w1;
    }
}

// ---------------- per-graph mean (both branches) ----------------
__global__ void graph_div2(const float* gsum, const float* gcnt,
                           float* xcg, float* xsg, float* oc, float* os) {
    int i = blockIdx.x * blockDim.x + threadIdx.x;
    if (i >= GG * HH) return;
    int g = i / HH;
    float inv = 1.f / fmaxf(gcnt[g], 1.f);
    float v = gsum[i] * inv;
    float w = gsum[GG * HH + i] * inv;
    xcg[i] = v; oc[i] = v;
    xsg[i] = w; os[i] = w;
}

// ---------------- fused heads (single block) ----------------
__device__ __forceinline__ void threefry2x32(uint32_t k0, uint32_t k1, uint32_t x0, uint32_t x1,
                                             uint32_t* o0, uint32_t* o1) {
    uint32_t ks[3] = {k0, k1, k0 ^ k1 ^ 0x1BD11BDAu};
    const int r1[4] = {13, 15, 26, 6};
    const int r2[4] = {17, 29, 16, 24};
    x0 += ks[0]; x1 += ks[1];
#pragma unroll
    for (int i = 0; i < 5; i++) {
        const int* rot = (i % 2 == 0) ? r1 : r2;
#pragma unroll
        for (int j = 0; j < 4; j++) {
            x0 += x1;
            x1 = (x1 << rot[j]) | (x1 >> (32 - rot[j]));
            x1 ^= x0;
        }
        x0 += ks[(i + 1) % 3];
        x1 += ks[(i + 2) % 3] + (uint32_t)(i + 1);
    }
    *o0 = x0; *o1 = x1;
}

__device__ void blk_bn(const float* in, float* out, int K) {
    int j = threadIdx.x;
    if (j < K) {
        float s = 0.f, s2 = 0.f;
        for (int m = 0; m < GG; m++) {
            float v = in[m * K + j];
            s += v; s2 += v * v;
        }
        float mean = s / GG;
        float var = s2 / GG - mean * mean;
        float r = rsqrtf(var + EPSF);
        for (int m = 0; m < GG; m++)
            out[m * K + j] = (in[m * K + j] - mean) * r + BETAF;
    }
    __syncthreads();
}

__device__ void blk_fc(const float* A, const float* W, const float* b, float* C,
                       int Kin, int Kout, int doRelu) {
    for (int i = threadIdx.x; i < GG * Kout; i += blockDim.x) {
        int m = i / Kout, j = i - m * Kout;
        float s = b ? b[j] : 0.f;
        for (int k = 0; k < Kin; k++) s = fmaf(A[m * Kin + k], W[k * Kout + j], s);
        C[i] = doRelu ? fmaxf(s, 0.f) : s;
    }
    __syncthreads();
}

__global__ void heads_kernel(
    const float* __restrict__ xcg, const float* __restrict__ xsg,
    const float* cfc1W, const float* cfc1b, const float* cfc2W, const float* cfc2b,
    const float* sfc1W, const float* sfc1b, const float* sfc2W, const float* sfc2b,
    const float* ccat1W, const float* ccat1b, const float* ccat2W, const float* ccat2b,
    float* h1, float* h2, float* h3, float* xcat,
    float* out_causal, float* out_spur, float* out_ctx) {
    __shared__ uint32_t keys[64];
    __shared__ int sperm[64];
    int tid = threadIdx.x;
    if (tid < 64) {
        uint32_t sk0, sk1, o0, o1;
        threefry2x32(0u, 42u, 0u, 1u, &sk0, &sk1);
        threefry2x32(sk0, sk1, 0u, (uint32_t)tid, &o0, &o1);
        keys[tid] = o0 ^ o1;
    }
    __syncthreads();
    if (tid < 64) {
        uint32_t ki = keys[tid];
        int rank = 0;
        for (int j = 0; j < 64; j++) {
            uint32_t kj = keys[j];
            rank += (kj < ki) || (kj == ki && j < tid);
        }
        sperm[rank] = tid;
    }
    __syncthreads();

    blk_bn(xcg, h1, 128);
    blk_fc(h1, cfc1W, cfc1b, h2, 128, DD, 1);
    blk_bn(h2, h3, DD);
    blk_fc(h3, cfc2W, cfc2b, out_causal, DD, CCH, 0);

    blk_bn(xsg, h1, 128);
    blk_fc(h1, sfc1W, sfc1b, h2, 128, DD, 1);
    blk_bn(h2, h3, DD);
    blk_fc(h3, sfc2W, sfc2b, h2, DD, CCH, 0);
    if (tid < GG) {
        float z0 = h2[tid * 2], z1 = h2[tid * 2 + 1];
        float m = fmaxf(z0, z1);
        float l = m + logf(expf(z0 - m) + expf(z1 - m));
        out_spur[tid * 2] = z0 - l;
        out_spur[tid * 2 + 1] = z1 - l;
    }
    __syncthreads();

    for (int i = tid; i < GG * 256; i += blockDim.x) {
        int g = i >> 8, c = i & 255;
        xcat[i] = (c < HH) ? xcg[g * HH + c] : xsg[sperm[g] * HH + (c - HH)];
    }
    __syncthreads();
    blk_bn(xcat, h1, 256);
    blk_fc(h1, ccat1W, ccat1b, h2, 256, DD, 1);
    blk_bn(h2, h3, DD);
    blk_fc(h3, ccat2W, ccat2b, out_ctx, DD, CCH, 0);
}

// ---------------- launch ----------------
extern "C" void kernel_launch(void* const* d_in, const int* in_sizes, int n_in,
                              void* d_out, int out_size) {
    const float* feat = nullptr;
    const int *src = nullptr, *dst = nullptr, *et = nullptr, *gid = nullptr;
    const float* Wp[27];
    int wi = 0, eseen = 0;
    for (int i = 0; i < n_in; i++) {
        int sz = in_sizes[i];
        if (sz == NN * BERTD) feat = (const float*)d_in[i];
        else if (sz == EE) {
            if (eseen == 0) src = (const int*)d_in[i];
            else if (eseen == 1) dst = (const int*)d_in[i];
            else et = (const int*)d_in[i];
            eseen++;
        } else if (sz == NN) gid = (const int*)d_in[i];
        else if (wi < 27) Wp[wi++] = (const float*)d_in[i];
    }
    const float *W_red = Wp[0], *b_red = Wp[1], *W_rel = Wp[2], *W_self = Wp[3], *b_rel = Wp[4];
    const float *W_conv = Wp[5], *b_conv = Wp[6], *W_eatt = Wp[7], *b_eatt = Wp[8];
    const float *W_natt = Wp[9], *b_natt = Wp[10], *W_cconv = Wp[11], *b_cconv = Wp[12];
    const float *W_sconv = Wp[13], *b_sconv = Wp[14];
    const float *cfc1W = Wp[15], *cfc1b = Wp[16], *cfc2W = Wp[17], *cfc2b = Wp[18];
    const float *sfc1W = Wp[19], *sfc1b = Wp[20], *sfc2W = Wp[21], *sfc2b = Wp[22];
    const float *ccat1W = Wp[23], *ccat1b = Wp[24], *ccat2W = Wp[25], *ccat2b = Wp[26];

    float *A, *B, *Cc, *S, *Wcat, *norms, *normd, *bsum, *bsq;
    float *gsum, *gcnt, *xcg, *xsg, *h1, *h2, *h3, *xcat, *geatt;
    int *din, *dout, *rowptr, *cursor, *eidx, *gsrc, *gett, *pos;
    cudaGetSymbolAddress((void**)&A, g_A);
    cudaGetSymbolAddress((void**)&B, g_B);
    cudaGetSymbolAddress((void**)&Cc, g_Cacc);
    cudaGetSymbolAddress((void**)&S, g_S);
    cudaGetSymbolAddress((void**)&Wcat, g_Wcat);
    cudaGetSymbolAddress((void**)&norms, g_norms);
    cudaGetSymbolAddress((void**)&normd, g_normd);
    cudaGetSymbolAddress((void**)&din, g_din);
    cudaGetSymbolAddress((void**)&dout, g_dout);
    cudaGetSymbolAddress((void**)&rowptr, g_rowptr);
    cudaGetSymbolAddress((void**)&cursor, g_cursor);
    cudaGetSymbolAddress((void**)&eidx, g_eidx);
    cudaGetSymbolAddress((void**)&gsrc, g_gsrc);
    cudaGetSymbolAddress((void**)&gett, g_gett);
    cudaGetSymbolAddress((void**)&pos, g_pos);
    cudaGetSymbolAddress((void**)&geatt, g_geatt);
    cudaGetSymbolAddress((void**)&bsum, g_sum);
    cudaGetSymbolAddress((void**)&bsq, g_sumsq);
    cudaGetSymbolAddress((void**)&gsum, g_gsum);
    cudaGetSymbolAddress((void**)&gcnt, g_gcnt);
    cudaGetSymbolAddress((void**)&xcg, g_xcg);
    cudaGetSymbolAddress((void**)&xsg, g_xsg);
    cudaGetSymbolAddress((void**)&h1, g_h1);
    cudaGetSymbolAddress((void**)&h2, g_h2);
    cudaGetSymbolAddress((void**)&h3, g_h3);
    cudaGetSymbolAddress((void**)&xcat, g_xcat);

    float* out = (float*)d_out;
    float* out_causal = out;
    float* out_spur = out + GG * CCH;
    float* out_ctx = out + 2 * GG * CCH;
    float* out_xcg = out + 3 * GG * CCH;
    float* out_xsg = out_xcg + GG * HH;
    float* out_natt = out_xsg + GG * HH;
    float* out_eatt = out_natt + NN * 2;

    const int gemmGrid = (NN + 127) / 128;
    const int edgeWGrid = (EE * 32 + 255) / 256;
    const int nodeWGrid = (NN * 32 + 255) / 256;
    const int gatherGrid = (NN + 7) / 8;
    const float invM = 1.f / NN;

    // side stream + events for captured fork/join (host-side resources only)
    cudaStream_t s1;
    cudaStreamCreateWithFlags(&s1, cudaStreamNonBlocking);
    cudaEvent_t evF1, evJ1, evF2, evJ2;
    cudaEventCreateWithFlags(&evF1, cudaEventDisableTiming);
    cudaEventCreateWithFlags(&evJ1, cudaEventDisableTiming);
    cudaEventCreateWithFlags(&evF2, cudaEventDisableTiming);
    cudaEventCreateWithFlags(&evJ2, cudaEventDisableTiming);

    // prologue on main stream
    prologue_fill<<<256, 256>>>(din, dout, cursor, bsum, bsq, gcnt, gsum);

    // fork 1: CSR build chain on s1, feat GEMM + stats on main
    cudaEventRecord(evF1, 0);
    cudaStreamWaitEvent(s1, evF1, 0);
    degree_int<<<(EE + 255) / 256, 256, 0, s1>>>(src, dst, dout, din, EE);
    make_norm2<<<(NN + 255) / 256, 256, 0, s1>>>(dout, din, gid, norms, normd, gcnt, NN);
    scan_rowptr<<<1, 1024, 0, s1>>>(din, rowptr, NN);
    build_eidx<<<(EE + 255) / 256, 256, 0, s1>>>(dst, src, et, rowptr, cursor, eidx,
                                                 gsrc, gett, pos, EE);
    build_wcat<<<(KCAT * HH + 255) / 256, 256, 0, s1>>>(W_rel, W_self, Wcat);
    cudaEventRecord(evJ1, s1);

    tgemm<<<gemmGrid, 256>>>(feat, W_red, b_red, A, NN, BERTD, 0, nullptr, nullptr,
                             nullptr, nullptr, nullptr, nullptr, 0);
    bn_stats<<<512, 128>>>(A, NN, bsum, bsq);
    cudaStreamWaitEvent(0, evJ1, 0);

    // RelGraphConv (aggregate-first, BN coefs inline from slot 0)
    csr_rel_gather_bn<<<gatherGrid, 256>>>(A, bsum, bsq, invM, gsrc, gett, rowptr, S, NN);
    tgemm<<<gemmGrid, 256>>>(S, Wcat, b_rel, A, NN, KCAT, 1, nullptr, nullptr,
                             nullptr, nullptr, nullptr, nullptr, 0);

    // two GraphConv layers (stats slots 1, 2)
    for (int i = 0; i < 2; i++) {
        float* ss = bsum + 128 * (i + 1);
        float* qq = bsq + 128 * (i + 1);
        bn_stats<<<512, 128>>>(A, NN, ss, qq);
        csr_gather_bn<<<gatherGrid, 256>>>(A, ss, qq, invM, norms, gsrc, rowptr, normd, Cc, NN);
        tgemm<<<gemmGrid, 256>>>(Cc, W_conv + (size_t)i * HH * HH, b_conv + i * HH, A, NN, HH, 1,
                                 nullptr, nullptr, nullptr, nullptr, nullptr, nullptr, 0);
    }

    // fork 2: edge attention on s1, node attention + branch stats on main
    cudaEventRecord(evF2, 0);
    cudaStreamWaitEvent(s1, evF2, 0);
    edge_att_kernel<<<edgeWGrid, 256, 0, s1>>>(A, src, dst, W_eatt, b_eatt, pos,
                                               out_eatt, geatt, EE);
    cudaEventRecord(evJ2, s1);

    node_att_kernel<<<nodeWGrid, 256>>>(A, W_natt, b_natt, out_natt, NN);
    bn_stats2<<<512, 128>>>(A, out_natt, NN, bsum + 384, bsq + 384);
    cudaStreamWaitEvent(0, evJ2, 0);

    csr_gather_bn2<<<gatherGrid, 256>>>(A, out_natt, bsum + 384, bsq + 384, invM,
                                        norms, gsrc, rowptr, geatt, normd, Cc, B, NN);

    // both branch GEMMs in ONE launch (fused pooling into gsum halves)
    tgemm<<<2 * gemmGrid, 256>>>(Cc, W_cconv, b_cconv, nullptr, NN, HH, 1, gid, gsum,
                                 B, W_sconv, b_sconv, gsum + GG * HH, gemmGrid);
    graph_div2<<<(GG * HH + 255) / 256, 256>>>(gsum, gcnt, xcg, xsg, out_xcg, out_xsg);

    // all three heads in one fused single-block kernel
    heads_kernel<<<1, 256>>>(xcg, xsg,
                             cfc1W, cfc1b, cfc2W, cfc2b,
                             sfc1W, sfc1b, sfc2W, sfc2b,
                             ccat1W, ccat1b, ccat2W, ccat2b,
                             h1, h2, h3, xcat,
                             out_causal, out_spur, out_ctx);
}